// round 13
// baseline (speedup 1.0000x reference)
#include <cuda_runtime.h>
#include <cstdint>
#include <cstdio>

// ---------------------------------------------------------------------------
// LiBNet forward, batch 512.  Round 13 = R12 (406us) + __launch_bounds__ to
// stop weight-array spills in conv1/gemm256 (R4 evidence: conv1 regs=32 with
// wr[48] live => local-memory reloads), + prep split so conv1 is profiled.
// ---------------------------------------------------------------------------

#define BATCH 512

// Scratch (device globals)
__device__ float   g_y1mx[512u*256u*64u];  // conv1 window max [b,16,16,64]
__device__ float   g_y1mn[512u*256u*64u];  // conv1 window min
__device__ int8_t  g_a1[512u*256u*64u];    // sign(pool(bn1)) [b,16,16,64]
__device__ int8_t  g_y2b[512u*256u*64u];   // conv2_1 out int8
__device__ int8_t  g_y3mx[512u*64u*256u];  // gemm64 window max [b,8,8,256]
__device__ int8_t  g_y3mn[512u*64u*256u];  // gemm64 window min
__device__ int8_t  g_a3[512u*64u*256u];    // sign(pool(bn2_2)) [b,8,8,256]
__device__ int8_t  g_y4b[512u*64u*256u];   // conv3_1 out int8
__device__ int16_t g_y5s[512u*64u*256u];   // conv3_2 out int16
__device__ float   g_w1s[48*64];           // sign(w1) transposed [k][c]
__device__ int8_t  g_wg2[32*64];           // sign(w2_1) transposed [k][c]
__device__ int8_t  g_wg3[32*256];          // sign(w3_1) transposed [k][c]
__device__ int8_t  g_wp2[256*64];          // sign(w2_2)
__device__ int8_t  g_wp3[256*256];         // sign(w3_2)
__device__ float   g_part[2097152];        // float stats partials (conv1 only)
__device__ long long g_ll[4*512];          // int stats [stage][{sum,sq}][256]
__device__ float   g_mean[256];
__device__ float   g_scale[256];
__device__ float   g_fcwr[16384*10];       // fc_w n-major over NHWC-flatten

#define ST_GRP2   0
#define ST_GEMM64 1
#define ST_GRP3   2
#define ST_G256   3

__device__ __forceinline__ void atomAddLL(long long* p, long long v) {
    atomicAdd((unsigned long long*)p, (unsigned long long)v);
}

__device__ __forceinline__ void finalize_channel(const long long* sbuf,
                                                 const float* gamma, int c,
                                                 double Pd, float* pm_out,
                                                 float* ps_out) {
    double mean = (double)sbuf[c] / Pd;
    double var  = (double)sbuf[256 + c] / Pd - mean * mean;
    double inv  = (double)gamma[c] / sqrt(var + 1e-5);
    double sh   = rint(log2(fabs(inv) + 1e-12));
    if (sh > 4.0) sh = 4.0;
    if (sh < -4.0) sh = -4.0;
    double sgn = (inv > 0.0) ? 1.0 : ((inv < 0.0) ? -1.0 : 0.0);
    *pm_out = (float)mean;
    *ps_out = (float)(sgn * exp2(sh));
}

// ---------------------------------------------------------------------------
// prep split into 3 kernels (so conv1 lands in profiled launch slot 4).
// ---------------------------------------------------------------------------
__global__ void prep_fcwr_kernel(const float* __restrict__ fcw,
                                 float* __restrict__ fcwr) {
    int i = blockIdx.x * 256 + threadIdx.x;  // i = n*16384 + e, e = hw*256 + c
    int n = i / 16384;
    int e = i % 16384;
    int c = e & 255, hw = e >> 8;
    fcwr[i] = fcw[n * 16384 + c * 64 + hw];
}

__global__ void prep_w_kernel(const float* __restrict__ w1,
                              const float* __restrict__ w2_1,
                              const float* __restrict__ w3_1,
                              const float* __restrict__ w2_2,
                              const float* __restrict__ w3_2,
                              float* __restrict__ w1s,
                              int8_t* __restrict__ wg2,
                              int8_t* __restrict__ wg3,
                              int8_t* __restrict__ wp2,
                              int8_t* __restrict__ wp3) {
    int bid = blockIdx.x, tid = threadIdx.x;
    if (bid < 256) {
        int i = bid * 256 + tid;
        float v = w3_2[i];
        wp3[i] = (int8_t)((v > 0.f) ? 1 : ((v < 0.f) ? -1 : 0));
    } else if (bid < 320) {
        int i = (bid - 256) * 256 + tid;
        float v = w2_2[i];
        wp2[i] = (int8_t)((v > 0.f) ? 1 : ((v < 0.f) ? -1 : 0));
    } else if (bid < 352) {
        int i = (bid - 320) * 256 + tid;  // i = k*256 + c
        int c = i & 255, k = i >> 8;
        float v = w3_1[c * 32 + k];
        wg3[i] = (int8_t)((v > 0.f) ? 1 : ((v < 0.f) ? -1 : 0));
    } else if (bid < 360) {
        int i = (bid - 352) * 256 + tid;  // i = k*64 + c
        int c = i & 63, k = i >> 6;
        float v = w2_1[c * 32 + k];
        wg2[i] = (int8_t)((v > 0.f) ? 1 : ((v < 0.f) ? -1 : 0));
    } else {
        int i = (bid - 360) * 256 + tid;  // i = k*64 + c
        int c = i & 63, k = i >> 6;
        float v = w1[c * 48 + k];
        w1s[i] = (v > 0.f) ? 1.f : ((v < 0.f) ? -1.f : 0.f);
    }
}

__global__ void prep_zero_kernel(long long* __restrict__ llbuf) {
    int tid = threadIdx.x;
#pragma unroll
    for (int q = 0; q < 8; q++) llbuf[q * 256 + tid] = 0;
}

// ---------------------------------------------------------------------------
// conv1: launch_bounds(256,3) -> 85-reg budget so wr[48] stays in registers.
// ---------------------------------------------------------------------------
__global__ void __launch_bounds__(256, 3)
conv1_kernel(const float* __restrict__ x,
             const float* __restrict__ w1s,
             float* __restrict__ ymx,
             float* __restrict__ ymn) {
    const int NS = 4096;
    int b = blockIdx.y, oy0 = blockIdx.x * 4;
    int tid = threadIdx.x;
    int c = tid & 63, xq = tid >> 6;

    __shared__ float xs[3][7][36];
    __shared__ float2 sred[256];

    for (int i = tid; i < 3 * 7 * 36; i += 256) {
        int col = i % 36;
        int r   = (i / 36) % 7;
        int ci  = i / 252;
        int ix = col - 1, iy = oy0 - 1 + r;
        float v = 0.f;
        if (ix >= 0 && ix < 32 && iy >= 0 && iy < 32)
            v = x[(((size_t)b * 3 + ci) * 32 + iy) * 32 + ix];
        xs[ci][r][col] = v;
    }

    float wr[48];
#pragma unroll
    for (int k = 0; k < 48; k++) wr[k] = w1s[k * 64 + c];
    __syncthreads();

    float s1 = 0.f, s2 = 0.f;
    float pmx[4], pmn[4];
#pragma unroll
    for (int r = 0; r < 4; r++) {
        float acc[8];
#pragma unroll
        for (int j = 0; j < 8; j++) acc[j] = 0.f;
#pragma unroll
        for (int ci = 0; ci < 3; ci++) {
#pragma unroll
            for (int kh = 0; kh < 4; kh++) {
                float rx[11];
#pragma unroll
                for (int t = 0; t < 11; t++) rx[t] = xs[ci][r + kh][xq * 8 + t];
#pragma unroll
                for (int kw = 0; kw < 4; kw++) {
                    float wv = wr[ci * 16 + kh * 4 + kw];
#pragma unroll
                    for (int j = 0; j < 8; j++) acc[j] += wv * rx[j + kw];
                }
            }
        }
#pragma unroll
        for (int j = 0; j < 8; j++) {
            s1 += acc[j];
            s2 += acc[j] * acc[j];
        }
        if ((r & 1) == 0) {
#pragma unroll
            for (int p = 0; p < 4; p++) {
                pmx[p] = fmaxf(acc[2 * p], acc[2 * p + 1]);
                pmn[p] = fminf(acc[2 * p], acc[2 * p + 1]);
            }
        } else {
            int poy = (oy0 >> 1) + (r >> 1);
#pragma unroll
            for (int p = 0; p < 4; p++) {
                float wmx = fmaxf(pmx[p], fmaxf(acc[2 * p], acc[2 * p + 1]));
                float wmn = fminf(pmn[p], fminf(acc[2 * p], acc[2 * p + 1]));
                size_t oi = (((size_t)b * 16 + poy) * 16 + xq * 4 + p) * 64 + c;
                ymx[oi] = wmx;
                ymn[oi] = wmn;
            }
        }
    }

    sred[tid] = make_float2(s1, s2);
    __syncthreads();
    if (tid < 64) {
        float2 a = sred[tid], b1 = sred[tid + 64], c1 = sred[tid + 128],
               d1 = sred[tid + 192];
        int slice = b * 8 + blockIdx.x;
        g_part[tid * NS + slice]        = a.x + b1.x + c1.x + d1.x;
        g_part[(64 + tid) * NS + slice] = a.y + b1.y + c1.y + d1.y;
    }
}

// rf for conv1 (float partials), writes g_mean/g_scale
template <int C>
__global__ void reduce_finalize_kernel(const float* __restrict__ gamma,
                                       int nslices, int P) {
    int c = blockIdx.x;
    int tid = threadIdx.x;
    float s1 = 0.f, s2 = 0.f;
    const float* p1 = g_part + (size_t)c * nslices;
    const float* p2 = g_part + (size_t)(C + c) * nslices;
#pragma unroll 4
    for (int s = tid; s < nslices; s += 256) {
        s1 += p1[s];
        s2 += p2[s];
    }
    __shared__ double sd1[256], sd2[256];
    sd1[tid] = (double)s1;
    sd2[tid] = (double)s2;
    __syncthreads();
    for (int s = 128; s > 0; s >>= 1) {
        if (tid < s) {
            sd1[tid] += sd1[tid + s];
            sd2[tid] += sd2[tid + s];
        }
        __syncthreads();
    }
    if (tid == 0) {
        double mean = sd1[0] / (double)P;
        double var  = sd2[0] / (double)P - mean * mean;
        double inv  = (double)gamma[c] / sqrt(var + 1e-5);
        double sh   = rint(log2(fabs(inv) + 1e-12));
        if (sh > 4.0) sh = 4.0;
        if (sh < -4.0) sh = -4.0;
        double sgn = (inv > 0.0) ? 1.0 : ((inv < 0.0) ? -1.0 : 0.0);
        g_mean[c]  = (float)mean;
        g_scale[c] = (float)(sgn * exp2(sh));
    }
}

// tiny finalize from integer sums -> g_mean/g_scale (for bn2_2 consumer)
__global__ void finalize_ll_kernel(const long long* __restrict__ sbuf,
                                   const float* __restrict__ gamma, int P) {
    int c = threadIdx.x;
    finalize_channel(sbuf, gamma, c, (double)P, &g_mean[c], &g_scale[c]);
}

// ---------------------------------------------------------------------------
// BN + pool-select + sign kernels.
// ---------------------------------------------------------------------------
__global__ void bn_poolsel_sign4_f_kernel(const float* __restrict__ ymx,
                                          const float* __restrict__ ymn,
                                          int8_t* __restrict__ out,
                                          const float* __restrict__ beta,
                                          int total4) {
    int idx = blockIdx.x * 256 + threadIdx.x;
    if (idx >= total4) return;
    int c = (idx * 4) & 63;
    float4 m  = *(const float4*)(g_mean + c);
    float4 s  = *(const float4*)(g_scale + c);
    float4 bt = *(const float4*)(beta + c);
    float4 vx = ((const float4*)ymx)[idx];
    float4 vn = ((const float4*)ymn)[idx];
    float v0 = (s.x > 0.f) ? vx.x : vn.x;
    float v1 = (s.y > 0.f) ? vx.y : vn.y;
    float v2 = (s.z > 0.f) ? vx.z : vn.z;
    float v3 = (s.w > 0.f) ? vx.w : vn.w;
    float r0 = (v0 - m.x) * s.x + bt.x;
    float r1 = (v1 - m.y) * s.y + bt.y;
    float r2 = (v2 - m.z) * s.z + bt.z;
    float r3 = (v3 - m.w) * s.w + bt.w;
    char4 o;
    o.x = (char)((r0 > 0.f) ? 1 : ((r0 < 0.f) ? -1 : 0));
    o.y = (char)((r1 > 0.f) ? 1 : ((r1 < 0.f) ? -1 : 0));
    o.z = (char)((r2 > 0.f) ? 1 : ((r2 < 0.f) ? -1 : 0));
    o.w = (char)((r3 > 0.f) ? 1 : ((r3 < 0.f) ? -1 : 0));
    ((char4*)out)[idx] = o;
}

__global__ void bn_poolsel_sign4_i8_kernel(const int8_t* __restrict__ ymx,
                                           const int8_t* __restrict__ ymn,
                                           int8_t* __restrict__ out,
                                           const float* __restrict__ beta,
                                           int total4) {
    int idx = blockIdx.x * 256 + threadIdx.x;
    if (idx >= total4) return;
    int c = (idx * 4) & 255;
    float4 m  = *(const float4*)(g_mean + c);
    float4 s  = *(const float4*)(g_scale + c);
    float4 bt = *(const float4*)(beta + c);
    char4 ux = ((const char4*)ymx)[idx];
    char4 un = ((const char4*)ymn)[idx];
    float v0 = (float)((s.x > 0.f) ? ux.x : un.x);
    float v1 = (float)((s.y > 0.f) ? ux.y : un.y);
    float v2 = (float)((s.z > 0.f) ? ux.z : un.z);
    float v3 = (float)((s.w > 0.f) ? ux.w : un.w);
    float r0 = (v0 - m.x) * s.x + bt.x;
    float r1 = (v1 - m.y) * s.y + bt.y;
    float r2 = (v2 - m.z) * s.z + bt.z;
    float r3 = (v3 - m.w) * s.w + bt.w;
    char4 o;
    o.x = (char)((r0 > 0.f) ? 1 : ((r0 < 0.f) ? -1 : 0));
    o.y = (char)((r1 > 0.f) ? 1 : ((r1 < 0.f) ? -1 : 0));
    o.z = (char)((r2 > 0.f) ? 1 : ((r2 < 0.f) ? -1 : 0));
    o.w = (char)((r3 > 0.f) ? 1 : ((r3 < 0.f) ? -1 : 0));
    ((char4*)out)[idx] = o;
}

// ---------------------------------------------------------------------------
// Grouped 4x4 binary conv: int16-pair LDS + dp4a; stats via ll atomics.
// ---------------------------------------------------------------------------
template <int H, int C>
__global__ void conv_grp_kernel(const int8_t* __restrict__ a,
                                const int8_t* __restrict__ wg,
                                int8_t* __restrict__ out,
                                long long* __restrict__ sbuf) {
    int b = blockIdx.y, oy = blockIdx.x;
    int tid = threadIdx.x;
    constexpr int PW = H + 3;
    __shared__ __align__(16) int8_t as[4][PW][C];
    __shared__ int2 sred[256];

    const int8_t* abase = a + (size_t)b * H * H * C;
    int total4 = (4 * PW * C) / 4;
    for (int i = tid; i < total4; i += 256) {
        int e = i * 4;
        int cc = e % C;
        int col = (e / C) % PW;
        int r = e / (C * PW);
        int ix = col - 1, iy = oy - 1 + r;
        int v = 0;
        if (ix >= 0 && ix < H && iy >= 0 && iy < H)
            v = *(const int*)(abase + ((size_t)iy * H + ix) * C + cc);
        *(int*)(&as[r][col][cc]) = v;
    }

    int c = tid % C;
    int xq = tid / C;
    int g2 = c & ~1;
    int wpair[16];
#pragma unroll
    for (int k = 0; k < 16; k++) {
        int w0 = (int)wg[k * C + c];
        int w1 = (int)wg[(16 + k) * C + c];
        wpair[k] = (w0 & 0xff) | ((w1 & 0xff) << 8);
    }
    __syncthreads();

    int is1 = 0, is2 = 0;
    constexpr int SPAN = (H * C) / 256;
    for (int j = 0; j < SPAN; j++) {
        int ox = xq * SPAN + j;
        int acc = 0;
#pragma unroll
        for (int kh = 0; kh < 4; kh++) {
#pragma unroll
            for (int kw = 0; kw < 4; kw++) {
                int v = (int)*(const uint16_t*)&as[kh][ox + kw][g2];
                acc = __dp4a(v, wpair[kh * 4 + kw], acc);
            }
        }
        out[(((size_t)b * H + oy) * H + ox) * C + c] = (int8_t)acc;
        is1 += acc;
        is2 += acc * acc;
    }

    if (C == 256) {
        atomAddLL(&sbuf[c], (long long)is1);
        atomAddLL(&sbuf[256 + c], (long long)is2);
    } else {
        sred[tid] = make_int2(is1, is2);
        __syncthreads();
        if (tid < C) {
            int a1 = 0, a2 = 0;
#pragma unroll
            for (int q = 0; q < 256 / C; q++) {
                a1 += sred[q * C + tid].x;
                a2 += sred[q * C + tid].y;
            }
            atomAddLL(&sbuf[tid], (long long)a1);
            atomAddLL(&sbuf[256 + tid], (long long)a2);
        }
    }
}

// ---------------------------------------------------------------------------
// gemm64: inline bn2_1 finalize; pre-pool (max,min); stats via ll atomics.
// ---------------------------------------------------------------------------
__global__ void gemm64_kernel(const int8_t* __restrict__ yin,
                              const int8_t* __restrict__ wp,
                              const float* __restrict__ gamma,
                              const float* __restrict__ beta,
                              const long long* __restrict__ stat_in,
                              long long* __restrict__ stat_out,
                              int8_t* __restrict__ omx,
                              int8_t* __restrict__ omn) {
    __shared__ __align__(16) int as[128][16];
    __shared__ float pm[64], ps[64], pb[64];
    int tid = threadIdx.x;
    if (tid < 64) {
        finalize_channel(stat_in, gamma, tid, 131072.0, &pm[tid], &ps[tid]);
        pb[tid] = beta[tid];
    }
    int c = tid;
    int wr[16];
    const int* w4 = (const int*)wp + c * 16;
#pragma unroll
    for (int k = 0; k < 16; k++) wr[k] = w4[k];
    __syncthreads();

    size_t p0 = (size_t)blockIdx.x * 128;
    const int* y4 = (const int*)(yin + p0 * 64);
    for (int i = tid; i < 2048; i += 256) {
        int c0 = (i & 15) * 4;
        int v = y4[i];
        float r0 = ((float)(char)(v)       - pm[c0])     * ps[c0]     + pb[c0];
        float r1 = ((float)(char)(v >> 8)  - pm[c0 + 1]) * ps[c0 + 1] + pb[c0 + 1];
        float r2 = ((float)(char)(v >> 16) - pm[c0 + 2]) * ps[c0 + 2] + pb[c0 + 2];
        float r3 = ((float)(char)(v >> 24) - pm[c0 + 3]) * ps[c0 + 3] + pb[c0 + 3];
        int u0 = (r0 > 0.f) ? 1 : ((r0 < 0.f) ? -1 : 0);
        int u1 = (r1 > 0.f) ? 1 : ((r1 < 0.f) ? -1 : 0);
        int u2 = (r2 > 0.f) ? 1 : ((r2 < 0.f) ? -1 : 0);
        int u3 = (r3 > 0.f) ? 1 : ((r3 < 0.f) ? -1 : 0);
        as[i >> 4][i & 15] =
            (u0 & 0xff) | ((u1 & 0xff) << 8) | ((u2 & 0xff) << 16) | (u3 << 24);
    }
    __syncthreads();

    int bimg = blockIdx.x >> 1;
    int prow0 = (blockIdx.x & 1) * 4;
    int is1 = 0, is2 = 0;
    int rpx[8], rpn[8];
    for (int lr = 0; lr < 8; lr++) {
#pragma unroll
        for (int cp = 0; cp < 8; cp++) {
            int a0, a1;
#pragma unroll
            for (int h = 0; h < 2; h++) {
                int p = lr * 16 + cp * 2 + h;
                int acc = 0;
                const int4* av = (const int4*)as[p];
#pragma unroll
                for (int k4 = 0; k4 < 4; k4++) {
                    int4 v = av[k4];
                    acc = __dp4a(v.x, wr[k4 * 4 + 0], acc);
                    acc = __dp4a(v.y, wr[k4 * 4 + 1], acc);
                    acc = __dp4a(v.z, wr[k4 * 4 + 2], acc);
                    acc = __dp4a(v.w, wr[k4 * 4 + 3], acc);
                }
                is1 += acc;
                is2 += acc * acc;
                if (h == 0) a0 = acc; else a1 = acc;
            }
            int hx = max(a0, a1), hn = min(a0, a1);
            if ((lr & 1) == 0) {
                rpx[cp] = hx;
                rpn[cp] = hn;
            } else {
                int wmx = max(rpx[cp], hx);
                int wmn = min(rpn[cp], hn);
                size_t oi = (((size_t)bimg * 8 + prow0 + (lr >> 1)) * 8 + cp) * 256 + c;
                omx[oi] = (int8_t)wmx;
                omn[oi] = (int8_t)wmn;
            }
        }
    }
    atomAddLL(&stat_out[c], (long long)is1);
    atomAddLL(&stat_out[256 + c], (long long)is2);
}

// gemm256: launch_bounds(256,3) so wr[64] stays in registers.
__global__ void __launch_bounds__(256, 3)
gemm256_kernel(const int8_t* __restrict__ yin,
               const int8_t* __restrict__ wp,
               const float* __restrict__ gamma,
               const float* __restrict__ beta,
               const long long* __restrict__ stat_in,
               long long* __restrict__ stat_out,
               int16_t* __restrict__ out) {
    __shared__ __align__(16) int as[64][64];
    __shared__ float pm[256], ps[256], pb[256];
    int tid = threadIdx.x;
    finalize_channel(stat_in, gamma, tid, 32768.0, &pm[tid], &ps[tid]);
    pb[tid] = beta[tid];
    int c = tid;
    int wr[64];
    const int* w4 = (const int*)wp + c * 64;
#pragma unroll
    for (int k = 0; k < 64; k++) wr[k] = w4[k];
    __syncthreads();

    size_t p0 = (size_t)blockIdx.x * 64;
    const int* y4 = (const int*)(yin + p0 * 256);
    for (int i = tid; i < 4096; i += 256) {
        int c0 = (i & 63) * 4;
        int v = y4[i];
        float r0 = ((float)(char)(v)       - pm[c0])     * ps[c0]     + pb[c0];
        float r1 = ((float)(char)(v >> 8)  - pm[c0 + 1]) * ps[c0 + 1] + pb[c0 + 1];
        float r2 = ((float)(char)(v >> 16) - pm[c0 + 2]) * ps[c0 + 2] + pb[c0 + 2];
        float r3 = ((float)(char)(v >> 24) - pm[c0 + 3]) * ps[c0 + 3] + pb[c0 + 3];
        int u0 = (r0 > 0.f) ? 1 : ((r0 < 0.f) ? -1 : 0);
        int u1 = (r1 > 0.f) ? 1 : ((r1 < 0.f) ? -1 : 0);
        int u2 = (r2 > 0.f) ? 1 : ((r2 < 0.f) ? -1 : 0);
        int u3 = (r3 > 0.f) ? 1 : ((r3 < 0.f) ? -1 : 0);
        as[i >> 6][i & 63] =
            (u0 & 0xff) | ((u1 & 0xff) << 8) | ((u2 & 0xff) << 16) | (u3 << 24);
    }
    __syncthreads();

    int is1 = 0, is2 = 0;
    for (int p = 0; p < 64; p++) {
        int acc = 0;
        const int4* av = (const int4*)as[p];
#pragma unroll
        for (int k4 = 0; k4 < 16; k4++) {
            int4 v = av[k4];
            acc = __dp4a(v.x, wr[k4 * 4 + 0], acc);
            acc = __dp4a(v.y, wr[k4 * 4 + 1], acc);
            acc = __dp4a(v.z, wr[k4 * 4 + 2], acc);
            acc = __dp4a(v.w, wr[k4 * 4 + 3], acc);
        }
        out[(p0 + p) * 256 + c] = (int16_t)acc;
        is1 += acc;
        is2 += acc * acc;
    }
    atomAddLL(&stat_out[c], (long long)is1);
    atomAddLL(&stat_out[256 + c], (long long)is2);
}

// ---------------------------------------------------------------------------
// FC with inline bn3_2 finalize; 4 batches per block; int16 input.
// ---------------------------------------------------------------------------
#define FCB 4
__global__ void fc_kernel(const int16_t* __restrict__ y5,
                          const float* __restrict__ fcwr,
                          const float* __restrict__ fc_b,
                          const float* __restrict__ gamma,
                          const float* __restrict__ beta,
                          const long long* __restrict__ stat_in,
                          float* __restrict__ out) {
    __shared__ float pm[256], ps[256], pb[256];
    int b0 = blockIdx.x * FCB;
    int tid = threadIdx.x;
    finalize_channel(stat_in, gamma, tid, 32768.0, &pm[tid], &ps[tid]);
    pb[tid] = beta[tid];
    __syncthreads();

    float acc[FCB][10];
#pragma unroll
    for (int bb = 0; bb < FCB; bb++)
#pragma unroll
        for (int n = 0; n < 10; n++) acc[bb][n] = 0.f;

    for (int i = tid; i < 16384; i += 256) {
        int c = i & 255;
        float m = pm[c], s = ps[c], bt = pb[c];
        float w[10];
#pragma unroll
        for (int n = 0; n < 10; n++) w[n] = fcwr[n * 16384 + i];
#pragma unroll
        for (int bb = 0; bb < FCB; bb++) {
            float v = ((float)y5[(size_t)(b0 + bb) * 16384 + i] - m) * s + bt;
#pragma unroll
            for (int n = 0; n < 10; n++) acc[bb][n] += v * w[n];
        }
    }

    __shared__ float sred[8][FCB * 10];
    int lane = tid & 31, wid = tid >> 5;
#pragma unroll
    for (int bb = 0; bb < FCB; bb++)
#pragma unroll
        for (int n = 0; n < 10; n++) {
            float v = acc[bb][n];
#pragma unroll
            for (int o = 16; o > 0; o >>= 1)
                v += __shfl_xor_sync(0xffffffffu, v, o);
            if (lane == 0) sred[wid][bb * 10 + n] = v;
        }
    __syncthreads();
    if (tid < FCB * 10) {
        float v = 0.f;
#pragma unroll
        for (int w8 = 0; w8 < 8; w8++) v += sred[w8][tid];
        int bb = tid / 10, n = tid % 10;
        out[(b0 + bb) * 10 + n] = v + fc_b[n];
    }
}

// ---------------------------------------------------------------------------
extern "C" void kernel_launch(void* const* d_in, const int* in_sizes, int n_in,
                              void* d_out, int out_size) {
    const float* x    = (const float*)d_in[0];
    const float* w1   = (const float*)d_in[1];
    const float* g1   = (const float*)d_in[2];
    const float* b1   = (const float*)d_in[3];
    const float* w2_1 = (const float*)d_in[4];
    const float* g2_1 = (const float*)d_in[5];
    const float* b2_1 = (const float*)d_in[6];
    const float* w2_2 = (const float*)d_in[7];
    const float* g2_2 = (const float*)d_in[8];
    const float* b2_2 = (const float*)d_in[9];
    const float* w3_1 = (const float*)d_in[10];
    const float* g3_1 = (const float*)d_in[11];
    const float* b3_1 = (const float*)d_in[12];
    const float* w3_2 = (const float*)d_in[13];
    const float* g3_2 = (const float*)d_in[14];
    const float* b3_2 = (const float*)d_in[15];
    const float* fcw  = (const float*)d_in[16];
    const float* fcb  = (const float*)d_in[17];
    float* out = (float*)d_out;

    float *y1mx, *y1mn, *fcwr, *w1s;
    int8_t *a1, *a3, *y2b, *y3mx, *y3mn, *y4b, *wp2, *wp3, *wg2, *wg3;
    int16_t *y5s;
    long long* llb;
    cudaGetSymbolAddress((void**)&y1mx, g_y1mx);
    cudaGetSymbolAddress((void**)&y1mn, g_y1mn);
    cudaGetSymbolAddress((void**)&y2b, g_y2b);
    cudaGetSymbolAddress((void**)&y3mx, g_y3mx);
    cudaGetSymbolAddress((void**)&y3mn, g_y3mn);
    cudaGetSymbolAddress((void**)&y4b, g_y4b);
    cudaGetSymbolAddress((void**)&y5s, g_y5s);
    cudaGetSymbolAddress((void**)&a1, g_a1);
    cudaGetSymbolAddress((void**)&a3, g_a3);
    cudaGetSymbolAddress((void**)&wp2, g_wp2);
    cudaGetSymbolAddress((void**)&wp3, g_wp3);
    cudaGetSymbolAddress((void**)&wg2, g_wg2);
    cudaGetSymbolAddress((void**)&wg3, g_wg3);
    cudaGetSymbolAddress((void**)&fcwr, g_fcwr);
    cudaGetSymbolAddress((void**)&w1s, g_w1s);
    cudaGetSymbolAddress((void**)&llb, g_ll);

    // 1-3: prep split (puts conv1 in profiled slot 4)
    prep_fcwr_kernel<<<640, 256>>>(fcw, fcwr);
    prep_w_kernel<<<372, 256>>>(w1, w2_1, w3_1, w2_2, w3_2,
                                w1s, wg2, wg3, wp2, wp3);
    prep_zero_kernel<<<1, 256>>>(llb);

    // 4-6: stage 1
    conv1_kernel<<<dim3(8, BATCH), 256>>>(x, w1s, y1mx, y1mn);
    reduce_finalize_kernel<64><<<64, 256>>>(g1, 4096, 512 * 1024);
    bn_poolsel_sign4_f_kernel<<<(512 * 256 * 64 / 4 + 255) / 256, 256>>>(
        y1mx, y1mn, a1, b1, 512 * 256 * 64 / 4);

    // 7-10: stage 2
    conv_grp_kernel<16, 64><<<dim3(16, BATCH), 256>>>(a1, wg2, y2b,
                                                      llb + ST_GRP2 * 512);
    gemm64_kernel<<<(512 * 256) / 128, 256>>>(y2b, wp2, g2_1, b2_1,
                                              llb + ST_GRP2 * 512,
                                              llb + ST_GEMM64 * 512,
                                              y3mx, y3mn);
    finalize_ll_kernel<<<1, 256>>>(llb + ST_GEMM64 * 512, g2_2, 131072);
    bn_poolsel_sign4_i8_kernel<<<(512 * 64 * 256 / 4 + 255) / 256, 256>>>(
        y3mx, y3mn, a3, b2_2, 512 * 64 * 256 / 4);

    // 11-12: stage 3
    conv_grp_kernel<8, 256><<<dim3(8, BATCH), 256>>>(a3, wg3, y4b,
                                                     llb + ST_GRP3 * 512);
    gemm256_kernel<<<(512 * 64) / 64, 256>>>(y4b, wp3, g3_1, b3_1,
                                             llb + ST_GRP3 * 512,
                                             llb + ST_G256 * 512, y5s);

    // 13: FC (bn3_2 finalize inline)
    fc_kernel<<<BATCH / FCB, 256>>>(y5s, fcwr, fcb, g3_2, b3_2,
                                    llb + ST_G256 * 512, out);
}

// round 14
// speedup vs baseline: 1.0273x; 1.0273x over previous
#include <cuda_runtime.h>
#include <cstdint>
#include <cstdio>

// ---------------------------------------------------------------------------
// LiBNet forward, batch 512.  Round 14 = R12 structure (405.8us) with conv1
// weights staged in SHARED memory (not registers -> no spill, no local-mem
// replays, natural occupancy). launch_bounds reverted (R13 lesson: occupancy
// beat register residency).
// ---------------------------------------------------------------------------

#define BATCH 512

// Scratch (device globals)
__device__ float   g_y1mx[512u*256u*64u];  // conv1 window max [b,16,16,64]
__device__ float   g_y1mn[512u*256u*64u];  // conv1 window min
__device__ int8_t  g_a1[512u*256u*64u];    // sign(pool(bn1)) [b,16,16,64]
__device__ int8_t  g_y2b[512u*256u*64u];   // conv2_1 out int8
__device__ int8_t  g_y3mx[512u*64u*256u];  // gemm64 window max [b,8,8,256]
__device__ int8_t  g_y3mn[512u*64u*256u];  // gemm64 window min
__device__ int8_t  g_a3[512u*64u*256u];    // sign(pool(bn2_2)) [b,8,8,256]
__device__ int8_t  g_y4b[512u*64u*256u];   // conv3_1 out int8
__device__ int16_t g_y5s[512u*64u*256u];   // conv3_2 out int16
__device__ float   g_w1s[48*64];           // sign(w1) transposed [k][c]
__device__ int8_t  g_wg2[32*64];           // sign(w2_1) transposed [k][c]
__device__ int8_t  g_wg3[32*256];          // sign(w3_1) transposed [k][c]
__device__ int8_t  g_wp2[256*64];          // sign(w2_2)
__device__ int8_t  g_wp3[256*256];         // sign(w3_2)
__device__ float   g_part[2097152];        // float stats partials (conv1 only)
__device__ long long g_ll[4*512];          // int stats [stage][{sum,sq}][256]
__device__ float   g_mean[256];
__device__ float   g_scale[256];
__device__ float   g_fcwr[16384*10];       // fc_w n-major over NHWC-flatten

#define ST_GRP2   0
#define ST_GEMM64 1
#define ST_GRP3   2
#define ST_G256   3

__device__ __forceinline__ void atomAddLL(long long* p, long long v) {
    atomicAdd((unsigned long long*)p, (unsigned long long)v);
}

__device__ __forceinline__ void finalize_channel(const long long* sbuf,
                                                 const float* gamma, int c,
                                                 double Pd, float* pm_out,
                                                 float* ps_out) {
    double mean = (double)sbuf[c] / Pd;
    double var  = (double)sbuf[256 + c] / Pd - mean * mean;
    double inv  = (double)gamma[c] / sqrt(var + 1e-5);
    double sh   = rint(log2(fabs(inv) + 1e-12));
    if (sh > 4.0) sh = 4.0;
    if (sh < -4.0) sh = -4.0;
    double sgn = (inv > 0.0) ? 1.0 : ((inv < 0.0) ? -1.0 : 0.0);
    *pm_out = (float)mean;
    *ps_out = (float)(sgn * exp2(sh));
}

// ---------------------------------------------------------------------------
// prep: all weight packing + zero the integer stat buffers (single kernel).
// ---------------------------------------------------------------------------
__global__ void prep_kernel(const float* __restrict__ w1,
                            const float* __restrict__ w2_1,
                            const float* __restrict__ w3_1,
                            const float* __restrict__ w2_2,
                            const float* __restrict__ w3_2,
                            const float* __restrict__ fcw,
                            float* __restrict__ w1s,
                            int8_t* __restrict__ wg2,
                            int8_t* __restrict__ wg3,
                            int8_t* __restrict__ wp2,
                            int8_t* __restrict__ wp3,
                            float* __restrict__ fcwr,
                            long long* __restrict__ llbuf) {
    int bid = blockIdx.x, tid = threadIdx.x;
    if (bid < 640) {
        int i = bid * 256 + tid;  // fcwr: i = n*16384 + e, e = hw*256 + c
        int n = i / 16384;
        int e = i % 16384;
        int c = e & 255, hw = e >> 8;
        fcwr[i] = fcw[n * 16384 + c * 64 + hw];
    } else if (bid < 896) {
        int i = (bid - 640) * 256 + tid;
        float v = w3_2[i];
        wp3[i] = (int8_t)((v > 0.f) ? 1 : ((v < 0.f) ? -1 : 0));
    } else if (bid < 960) {
        int i = (bid - 896) * 256 + tid;
        float v = w2_2[i];
        wp2[i] = (int8_t)((v > 0.f) ? 1 : ((v < 0.f) ? -1 : 0));
    } else if (bid < 992) {
        int i = (bid - 960) * 256 + tid;  // i = k*256 + c
        int c = i & 255, k = i >> 8;
        float v = w3_1[c * 32 + k];
        wg3[i] = (int8_t)((v > 0.f) ? 1 : ((v < 0.f) ? -1 : 0));
    } else if (bid < 1000) {
        int i = (bid - 992) * 256 + tid;  // i = k*64 + c
        int c = i & 63, k = i >> 6;
        float v = w2_1[c * 32 + k];
        wg2[i] = (int8_t)((v > 0.f) ? 1 : ((v < 0.f) ? -1 : 0));
    } else if (bid < 1012) {
        int i = (bid - 1000) * 256 + tid;  // i = k*64 + c
        int c = i & 63, k = i >> 6;
        float v = w1[c * 48 + k];
        w1s[i] = (v > 0.f) ? 1.f : ((v < 0.f) ? -1.f : 0.f);
    } else {
#pragma unroll
        for (int q = 0; q < 8; q++) llbuf[q * 256 + tid] = 0;
    }
}

// ---------------------------------------------------------------------------
// conv1: weights staged in SMEM (ws[k*64+c], lane-consecutive c -> conflict-
// free; 1 LDS per 8 FMAs). ~30 live regs, no spill, natural occupancy.
// ---------------------------------------------------------------------------
__global__ void conv1_kernel(const float* __restrict__ x,
                             const float* __restrict__ w1s,
                             float* __restrict__ ymx,
                             float* __restrict__ ymn) {
    const int NS = 4096;
    int b = blockIdx.y, oy0 = blockIdx.x * 4;
    int tid = threadIdx.x;
    int c = tid & 63, xq = tid >> 6;

    __shared__ float xs[3][7][36];
    __shared__ float ws[3072];  // [k][c], 12 KB
    __shared__ float2 sred[256];

    for (int i = tid; i < 3072; i += 256) ws[i] = w1s[i];
    for (int i = tid; i < 3 * 7 * 36; i += 256) {
        int col = i % 36;
        int r   = (i / 36) % 7;
        int ci  = i / 252;
        int ix = col - 1, iy = oy0 - 1 + r;
        float v = 0.f;
        if (ix >= 0 && ix < 32 && iy >= 0 && iy < 32)
            v = x[(((size_t)b * 3 + ci) * 32 + iy) * 32 + ix];
        xs[ci][r][col] = v;
    }
    __syncthreads();

    float s1 = 0.f, s2 = 0.f;
    float pmx[4], pmn[4];
#pragma unroll
    for (int r = 0; r < 4; r++) {
        float acc[8];
#pragma unroll
        for (int j = 0; j < 8; j++) acc[j] = 0.f;
#pragma unroll
        for (int ci = 0; ci < 3; ci++) {
#pragma unroll
            for (int kh = 0; kh < 4; kh++) {
                float rx[11];
#pragma unroll
                for (int t = 0; t < 11; t++) rx[t] = xs[ci][r + kh][xq * 8 + t];
#pragma unroll
                for (int kw = 0; kw < 4; kw++) {
                    float wv = ws[(ci * 16 + kh * 4 + kw) * 64 + c];
#pragma unroll
                    for (int j = 0; j < 8; j++) acc[j] += wv * rx[j + kw];
                }
            }
        }
#pragma unroll
        for (int j = 0; j < 8; j++) {
            s1 += acc[j];
            s2 += acc[j] * acc[j];
        }
        if ((r & 1) == 0) {
#pragma unroll
            for (int p = 0; p < 4; p++) {
                pmx[p] = fmaxf(acc[2 * p], acc[2 * p + 1]);
                pmn[p] = fminf(acc[2 * p], acc[2 * p + 1]);
            }
        } else {
            int poy = (oy0 >> 1) + (r >> 1);
#pragma unroll
            for (int p = 0; p < 4; p++) {
                float wmx = fmaxf(pmx[p], fmaxf(acc[2 * p], acc[2 * p + 1]));
                float wmn = fminf(pmn[p], fminf(acc[2 * p], acc[2 * p + 1]));
                size_t oi = (((size_t)b * 16 + poy) * 16 + xq * 4 + p) * 64 + c;
                ymx[oi] = wmx;
                ymn[oi] = wmn;
            }
        }
    }

    sred[tid] = make_float2(s1, s2);
    __syncthreads();
    if (tid < 64) {
        float2 a = sred[tid], b1 = sred[tid + 64], c1 = sred[tid + 128],
               d1 = sred[tid + 192];
        int slice = b * 8 + blockIdx.x;
        g_part[tid * NS + slice]        = a.x + b1.x + c1.x + d1.x;
        g_part[(64 + tid) * NS + slice] = a.y + b1.y + c1.y + d1.y;
    }
}

// rf for conv1 (float partials), writes g_mean/g_scale
template <int C>
__global__ void reduce_finalize_kernel(const float* __restrict__ gamma,
                                       int nslices, int P) {
    int c = blockIdx.x;
    int tid = threadIdx.x;
    float s1 = 0.f, s2 = 0.f;
    const float* p1 = g_part + (size_t)c * nslices;
    const float* p2 = g_part + (size_t)(C + c) * nslices;
#pragma unroll 4
    for (int s = tid; s < nslices; s += 256) {
        s1 += p1[s];
        s2 += p2[s];
    }
    __shared__ double sd1[256], sd2[256];
    sd1[tid] = (double)s1;
    sd2[tid] = (double)s2;
    __syncthreads();
    for (int s = 128; s > 0; s >>= 1) {
        if (tid < s) {
            sd1[tid] += sd1[tid + s];
            sd2[tid] += sd2[tid + s];
        }
        __syncthreads();
    }
    if (tid == 0) {
        double mean = sd1[0] / (double)P;
        double var  = sd2[0] / (double)P - mean * mean;
        double inv  = (double)gamma[c] / sqrt(var + 1e-5);
        double sh   = rint(log2(fabs(inv) + 1e-12));
        if (sh > 4.0) sh = 4.0;
        if (sh < -4.0) sh = -4.0;
        double sgn = (inv > 0.0) ? 1.0 : ((inv < 0.0) ? -1.0 : 0.0);
        g_mean[c]  = (float)mean;
        g_scale[c] = (float)(sgn * exp2(sh));
    }
}

// tiny finalize from integer sums -> g_mean/g_scale (for bn2_2 consumer)
__global__ void finalize_ll_kernel(const long long* __restrict__ sbuf,
                                   const float* __restrict__ gamma, int P) {
    int c = threadIdx.x;
    finalize_channel(sbuf, gamma, c, (double)P, &g_mean[c], &g_scale[c]);
}

// ---------------------------------------------------------------------------
// BN + pool-select + sign kernels.
// ---------------------------------------------------------------------------
__global__ void bn_poolsel_sign4_f_kernel(const float* __restrict__ ymx,
                                          const float* __restrict__ ymn,
                                          int8_t* __restrict__ out,
                                          const float* __restrict__ beta,
                                          int total4) {
    int idx = blockIdx.x * 256 + threadIdx.x;
    if (idx >= total4) return;
    int c = (idx * 4) & 63;
    float4 m  = *(const float4*)(g_mean + c);
    float4 s  = *(const float4*)(g_scale + c);
    float4 bt = *(const float4*)(beta + c);
    float4 vx = ((const float4*)ymx)[idx];
    float4 vn = ((const float4*)ymn)[idx];
    float v0 = (s.x > 0.f) ? vx.x : vn.x;
    float v1 = (s.y > 0.f) ? vx.y : vn.y;
    float v2 = (s.z > 0.f) ? vx.z : vn.z;
    float v3 = (s.w > 0.f) ? vx.w : vn.w;
    float r0 = (v0 - m.x) * s.x + bt.x;
    float r1 = (v1 - m.y) * s.y + bt.y;
    float r2 = (v2 - m.z) * s.z + bt.z;
    float r3 = (v3 - m.w) * s.w + bt.w;
    char4 o;
    o.x = (char)((r0 > 0.f) ? 1 : ((r0 < 0.f) ? -1 : 0));
    o.y = (char)((r1 > 0.f) ? 1 : ((r1 < 0.f) ? -1 : 0));
    o.z = (char)((r2 > 0.f) ? 1 : ((r2 < 0.f) ? -1 : 0));
    o.w = (char)((r3 > 0.f) ? 1 : ((r3 < 0.f) ? -1 : 0));
    ((char4*)out)[idx] = o;
}

__global__ void bn_poolsel_sign4_i8_kernel(const int8_t* __restrict__ ymx,
                                           const int8_t* __restrict__ ymn,
                                           int8_t* __restrict__ out,
                                           const float* __restrict__ beta,
                                           int total4) {
    int idx = blockIdx.x * 256 + threadIdx.x;
    if (idx >= total4) return;
    int c = (idx * 4) & 255;
    float4 m  = *(const float4*)(g_mean + c);
    float4 s  = *(const float4*)(g_scale + c);
    float4 bt = *(const float4*)(beta + c);
    char4 ux = ((const char4*)ymx)[idx];
    char4 un = ((const char4*)ymn)[idx];
    float v0 = (float)((s.x > 0.f) ? ux.x : un.x);
    float v1 = (float)((s.y > 0.f) ? ux.y : un.y);
    float v2 = (float)((s.z > 0.f) ? ux.z : un.z);
    float v3 = (float)((s.w > 0.f) ? ux.w : un.w);
    float r0 = (v0 - m.x) * s.x + bt.x;
    float r1 = (v1 - m.y) * s.y + bt.y;
    float r2 = (v2 - m.z) * s.z + bt.z;
    float r3 = (v3 - m.w) * s.w + bt.w;
    char4 o;
    o.x = (char)((r0 > 0.f) ? 1 : ((r0 < 0.f) ? -1 : 0));
    o.y = (char)((r1 > 0.f) ? 1 : ((r1 < 0.f) ? -1 : 0));
    o.z = (char)((r2 > 0.f) ? 1 : ((r2 < 0.f) ? -1 : 0));
    o.w = (char)((r3 > 0.f) ? 1 : ((r3 < 0.f) ? -1 : 0));
    ((char4*)out)[idx] = o;
}

// ---------------------------------------------------------------------------
// Grouped 4x4 binary conv: int16-pair LDS + dp4a; stats via ll atomics.
// ---------------------------------------------------------------------------
template <int H, int C>
__global__ void conv_grp_kernel(const int8_t* __restrict__ a,
                                const int8_t* __restrict__ wg,
                                int8_t* __restrict__ out,
                                long long* __restrict__ sbuf) {
    int b = blockIdx.y, oy = blockIdx.x;
    int tid = threadIdx.x;
    constexpr int PW = H + 3;
    __shared__ __align__(16) int8_t as[4][PW][C];
    __shared__ int2 sred[256];

    const int8_t* abase = a + (size_t)b * H * H * C;
    int total4 = (4 * PW * C) / 4;
    for (int i = tid; i < total4; i += 256) {
        int e = i * 4;
        int cc = e % C;
        int col = (e / C) % PW;
        int r = e / (C * PW);
        int ix = col - 1, iy = oy - 1 + r;
        int v = 0;
        if (ix >= 0 && ix < H && iy >= 0 && iy < H)
            v = *(const int*)(abase + ((size_t)iy * H + ix) * C + cc);
        *(int*)(&as[r][col][cc]) = v;
    }

    int c = tid % C;
    int xq = tid / C;
    int g2 = c & ~1;
    int wpair[16];
#pragma unroll
    for (int k = 0; k < 16; k++) {
        int w0 = (int)wg[k * C + c];
        int w1 = (int)wg[(16 + k) * C + c];
        wpair[k] = (w0 & 0xff) | ((w1 & 0xff) << 8);
    }
    __syncthreads();

    int is1 = 0, is2 = 0;
    constexpr int SPAN = (H * C) / 256;
    for (int j = 0; j < SPAN; j++) {
        int ox = xq * SPAN + j;
        int acc = 0;
#pragma unroll
        for (int kh = 0; kh < 4; kh++) {
#pragma unroll
            for (int kw = 0; kw < 4; kw++) {
                int v = (int)*(const uint16_t*)&as[kh][ox + kw][g2];
                acc = __dp4a(v, wpair[kh * 4 + kw], acc);
            }
        }
        out[(((size_t)b * H + oy) * H + ox) * C + c] = (int8_t)acc;
        is1 += acc;
        is2 += acc * acc;
    }

    if (C == 256) {
        atomAddLL(&sbuf[c], (long long)is1);
        atomAddLL(&sbuf[256 + c], (long long)is2);
    } else {
        sred[tid] = make_int2(is1, is2);
        __syncthreads();
        if (tid < C) {
            int a1 = 0, a2 = 0;
#pragma unroll
            for (int q = 0; q < 256 / C; q++) {
                a1 += sred[q * C + tid].x;
                a2 += sred[q * C + tid].y;
            }
            atomAddLL(&sbuf[tid], (long long)a1);
            atomAddLL(&sbuf[256 + tid], (long long)a2);
        }
    }
}

// ---------------------------------------------------------------------------
// gemm64: inline bn2_1 finalize; pre-pool (max,min); stats via ll atomics.
// ---------------------------------------------------------------------------
__global__ void gemm64_kernel(const int8_t* __restrict__ yin,
                              const int8_t* __restrict__ wp,
                              const float* __restrict__ gamma,
                              const float* __restrict__ beta,
                              const long long* __restrict__ stat_in,
                              long long* __restrict__ stat_out,
                              int8_t* __restrict__ omx,
                              int8_t* __restrict__ omn) {
    __shared__ __align__(16) int as[128][16];
    __shared__ float pm[64], ps[64], pb[64];
    int tid = threadIdx.x;
    if (tid < 64) {
        finalize_channel(stat_in, gamma, tid, 131072.0, &pm[tid], &ps[tid]);
        pb[tid] = beta[tid];
    }
    int c = tid;
    int wr[16];
    const int* w4 = (const int*)wp + c * 16;
#pragma unroll
    for (int k = 0; k < 16; k++) wr[k] = w4[k];
    __syncthreads();

    size_t p0 = (size_t)blockIdx.x * 128;
    const int* y4 = (const int*)(yin + p0 * 64);
    for (int i = tid; i < 2048; i += 256) {
        int c0 = (i & 15) * 4;
        int v = y4[i];
        float r0 = ((float)(char)(v)       - pm[c0])     * ps[c0]     + pb[c0];
        float r1 = ((float)(char)(v >> 8)  - pm[c0 + 1]) * ps[c0 + 1] + pb[c0 + 1];
        float r2 = ((float)(char)(v >> 16) - pm[c0 + 2]) * ps[c0 + 2] + pb[c0 + 2];
        float r3 = ((float)(char)(v >> 24) - pm[c0 + 3]) * ps[c0 + 3] + pb[c0 + 3];
        int u0 = (r0 > 0.f) ? 1 : ((r0 < 0.f) ? -1 : 0);
        int u1 = (r1 > 0.f) ? 1 : ((r1 < 0.f) ? -1 : 0);
        int u2 = (r2 > 0.f) ? 1 : ((r2 < 0.f) ? -1 : 0);
        int u3 = (r3 > 0.f) ? 1 : ((r3 < 0.f) ? -1 : 0);
        as[i >> 4][i & 15] =
            (u0 & 0xff) | ((u1 & 0xff) << 8) | ((u2 & 0xff) << 16) | (u3 << 24);
    }
    __syncthreads();

    int bimg = blockIdx.x >> 1;
    int prow0 = (blockIdx.x & 1) * 4;
    int is1 = 0, is2 = 0;
    int rpx[8], rpn[8];
    for (int lr = 0; lr < 8; lr++) {
#pragma unroll
        for (int cp = 0; cp < 8; cp++) {
            int a0, a1;
#pragma unroll
            for (int h = 0; h < 2; h++) {
                int p = lr * 16 + cp * 2 + h;
                int acc = 0;
                const int4* av = (const int4*)as[p];
#pragma unroll
                for (int k4 = 0; k4 < 4; k4++) {
                    int4 v = av[k4];
                    acc = __dp4a(v.x, wr[k4 * 4 + 0], acc);
                    acc = __dp4a(v.y, wr[k4 * 4 + 1], acc);
                    acc = __dp4a(v.z, wr[k4 * 4 + 2], acc);
                    acc = __dp4a(v.w, wr[k4 * 4 + 3], acc);
                }
                is1 += acc;
                is2 += acc * acc;
                if (h == 0) a0 = acc; else a1 = acc;
            }
            int hx = max(a0, a1), hn = min(a0, a1);
            if ((lr & 1) == 0) {
                rpx[cp] = hx;
                rpn[cp] = hn;
            } else {
                int wmx = max(rpx[cp], hx);
                int wmn = min(rpn[cp], hn);
                size_t oi = (((size_t)bimg * 8 + prow0 + (lr >> 1)) * 8 + cp) * 256 + c;
                omx[oi] = (int8_t)wmx;
                omn[oi] = (int8_t)wmn;
            }
        }
    }
    atomAddLL(&stat_out[c], (long long)is1);
    atomAddLL(&stat_out[256 + c], (long long)is2);
}

// gemm256: inline bn3_1 finalize; stats via ll atomics (no launch bounds).
__global__ void gemm256_kernel(const int8_t* __restrict__ yin,
                               const int8_t* __restrict__ wp,
                               const float* __restrict__ gamma,
                               const float* __restrict__ beta,
                               const long long* __restrict__ stat_in,
                               long long* __restrict__ stat_out,
                               int16_t* __restrict__ out) {
    __shared__ __align__(16) int as[64][64];
    __shared__ float pm[256], ps[256], pb[256];
    int tid = threadIdx.x;
    finalize_channel(stat_in, gamma, tid, 32768.0, &pm[tid], &ps[tid]);
    pb[tid] = beta[tid];
    int c = tid;
    int wr[64];
    const int* w4 = (const int*)wp + c * 64;
#pragma unroll
    for (int k = 0; k < 64; k++) wr[k] = w4[k];
    __syncthreads();

    size_t p0 = (size_t)blockIdx.x * 64;
    const int* y4 = (const int*)(yin + p0 * 256);
    for (int i = tid; i < 4096; i += 256) {
        int c0 = (i & 63) * 4;
        int v = y4[i];
        float r0 = ((float)(char)(v)       - pm[c0])     * ps[c0]     + pb[c0];
        float r1 = ((float)(char)(v >> 8)  - pm[c0 + 1]) * ps[c0 + 1] + pb[c0 + 1];
        float r2 = ((float)(char)(v >> 16) - pm[c0 + 2]) * ps[c0 + 2] + pb[c0 + 2];
        float r3 = ((float)(char)(v >> 24) - pm[c0 + 3]) * ps[c0 + 3] + pb[c0 + 3];
        int u0 = (r0 > 0.f) ? 1 : ((r0 < 0.f) ? -1 : 0);
        int u1 = (r1 > 0.f) ? 1 : ((r1 < 0.f) ? -1 : 0);
        int u2 = (r2 > 0.f) ? 1 : ((r2 < 0.f) ? -1 : 0);
        int u3 = (r3 > 0.f) ? 1 : ((r3 < 0.f) ? -1 : 0);
        as[i >> 6][i & 63] =
            (u0 & 0xff) | ((u1 & 0xff) << 8) | ((u2 & 0xff) << 16) | (u3 << 24);
    }
    __syncthreads();

    int is1 = 0, is2 = 0;
    for (int p = 0; p < 64; p++) {
        int acc = 0;
        const int4* av = (const int4*)as[p];
#pragma unroll
        for (int k4 = 0; k4 < 16; k4++) {
            int4 v = av[k4];
            acc = __dp4a(v.x, wr[k4 * 4 + 0], acc);
            acc = __dp4a(v.y, wr[k4 * 4 + 1], acc);
            acc = __dp4a(v.z, wr[k4 * 4 + 2], acc);
            acc = __dp4a(v.w, wr[k4 * 4 + 3], acc);
        }
        out[(p0 + p) * 256 + c] = (int16_t)acc;
        is1 += acc;
        is2 += acc * acc;
    }
    atomAddLL(&stat_out[c], (long long)is1);
    atomAddLL(&stat_out[256 + c], (long long)is2);
}

// ---------------------------------------------------------------------------
// FC with inline bn3_2 finalize; 4 batches per block; int16 input.
// ---------------------------------------------------------------------------
#define FCB 4
__global__ void fc_kernel(const int16_t* __restrict__ y5,
                          const float* __restrict__ fcwr,
                          const float* __restrict__ fc_b,
                          const float* __restrict__ gamma,
                          const float* __restrict__ beta,
                          const long long* __restrict__ stat_in,
                          float* __restrict__ out) {
    __shared__ float pm[256], ps[256], pb[256];
    int b0 = blockIdx.x * FCB;
    int tid = threadIdx.x;
    finalize_channel(stat_in, gamma, tid, 32768.0, &pm[tid], &ps[tid]);
    pb[tid] = beta[tid];
    __syncthreads();

    float acc[FCB][10];
#pragma unroll
    for (int bb = 0; bb < FCB; bb++)
#pragma unroll
        for (int n = 0; n < 10; n++) acc[bb][n] = 0.f;

    for (int i = tid; i < 16384; i += 256) {
        int c = i & 255;
        float m = pm[c], s = ps[c], bt = pb[c];
        float w[10];
#pragma unroll
        for (int n = 0; n < 10; n++) w[n] = fcwr[n * 16384 + i];
#pragma unroll
        for (int bb = 0; bb < FCB; bb++) {
            float v = ((float)y5[(size_t)(b0 + bb) * 16384 + i] - m) * s + bt;
#pragma unroll
            for (int n = 0; n < 10; n++) acc[bb][n] += v * w[n];
        }
    }

    __shared__ float sred[8][FCB * 10];
    int lane = tid & 31, wid = tid >> 5;
#pragma unroll
    for (int bb = 0; bb < FCB; bb++)
#pragma unroll
        for (int n = 0; n < 10; n++) {
            float v = acc[bb][n];
#pragma unroll
            for (int o = 16; o > 0; o >>= 1)
                v += __shfl_xor_sync(0xffffffffu, v, o);
            if (lane == 0) sred[wid][bb * 10 + n] = v;
        }
    __syncthreads();
    if (tid < FCB * 10) {
        float v = 0.f;
#pragma unroll
        for (int w8 = 0; w8 < 8; w8++) v += sred[w8][tid];
        int bb = tid / 10, n = tid % 10;
        out[(b0 + bb) * 10 + n] = v + fc_b[n];
    }
}

// ---------------------------------------------------------------------------
extern "C" void kernel_launch(void* const* d_in, const int* in_sizes, int n_in,
                              void* d_out, int out_size) {
    const float* x    = (const float*)d_in[0];
    const float* w1   = (const float*)d_in[1];
    const float* g1   = (const float*)d_in[2];
    const float* b1   = (const float*)d_in[3];
    const float* w2_1 = (const float*)d_in[4];
    const float* g2_1 = (const float*)d_in[5];
    const float* b2_1 = (const float*)d_in[6];
    const float* w2_2 = (const float*)d_in[7];
    const float* g2_2 = (const float*)d_in[8];
    const float* b2_2 = (const float*)d_in[9];
    const float* w3_1 = (const float*)d_in[10];
    const float* g3_1 = (const float*)d_in[11];
    const float* b3_1 = (const float*)d_in[12];
    const float* w3_2 = (const float*)d_in[13];
    const float* g3_2 = (const float*)d_in[14];
    const float* b3_2 = (const float*)d_in[15];
    const float* fcw  = (const float*)d_in[16];
    const float* fcb  = (const float*)d_in[17];
    float* out = (float*)d_out;

    float *y1mx, *y1mn, *fcwr, *w1s;
    int8_t *a1, *a3, *y2b, *y3mx, *y3mn, *y4b, *wp2, *wp3, *wg2, *wg3;
    int16_t *y5s;
    long long* llb;
    cudaGetSymbolAddress((void**)&y1mx, g_y1mx);
    cudaGetSymbolAddress((void**)&y1mn, g_y1mn);
    cudaGetSymbolAddress((void**)&y2b, g_y2b);
    cudaGetSymbolAddress((void**)&y3mx, g_y3mx);
    cudaGetSymbolAddress((void**)&y3mn, g_y3mn);
    cudaGetSymbolAddress((void**)&y4b, g_y4b);
    cudaGetSymbolAddress((void**)&y5s, g_y5s);
    cudaGetSymbolAddress((void**)&a1, g_a1);
    cudaGetSymbolAddress((void**)&a3, g_a3);
    cudaGetSymbolAddress((void**)&wp2, g_wp2);
    cudaGetSymbolAddress((void**)&wp3, g_wp3);
    cudaGetSymbolAddress((void**)&wg2, g_wg2);
    cudaGetSymbolAddress((void**)&wg3, g_wg3);
    cudaGetSymbolAddress((void**)&fcwr, g_fcwr);
    cudaGetSymbolAddress((void**)&w1s, g_w1s);
    cudaGetSymbolAddress((void**)&llb, g_ll);

    // 1: weight prep + zero int stat buffers
    prep_kernel<<<1013, 256>>>(w1, w2_1, w3_1, w2_2, w3_2, fcw,
                               w1s, wg2, wg3, wp2, wp3, fcwr, llb);

    // 2-4: stage 1 (bn_poolsel_f in profiled slot 4 as control)
    conv1_kernel<<<dim3(8, BATCH), 256>>>(x, w1s, y1mx, y1mn);
    reduce_finalize_kernel<64><<<64, 256>>>(g1, 4096, 512 * 1024);
    bn_poolsel_sign4_f_kernel<<<(512 * 256 * 64 / 4 + 255) / 256, 256>>>(
        y1mx, y1mn, a1, b1, 512 * 256 * 64 / 4);

    // 5-8: stage 2
    conv_grp_kernel<16, 64><<<dim3(16, BATCH), 256>>>(a1, wg2, y2b,
                                                      llb + ST_GRP2 * 512);
    gemm64_kernel<<<(512 * 256) / 128, 256>>>(y2b, wp2, g2_1, b2_1,
                                              llb + ST_GRP2 * 512,
                                              llb + ST_GEMM64 * 512,
                                              y3mx, y3mn);
    finalize_ll_kernel<<<1, 256>>>(llb + ST_GEMM64 * 512, g2_2, 131072);
    bn_poolsel_sign4_i8_kernel<<<(512 * 64 * 256 / 4 + 255) / 256, 256>>>(
        y3mx, y3mn, a3, b2_2, 512 * 64 * 256 / 4);

    // 9-10: stage 3
    conv_grp_kernel<8, 256><<<dim3(8, BATCH), 256>>>(a3, wg3, y4b,
                                                     llb + ST_GRP3 * 512);
    gemm256_kernel<<<(512 * 64) / 64, 256>>>(y4b, wp3, g3_1, b3_1,
                                             llb + ST_GRP3 * 512,
                                             llb + ST_G256 * 512, y5s);

    // 11: FC (bn3_2 finalize inline)
    fc_kernel<<<BATCH / FCB, 256>>>(y5s, fcwr, fcb, g3_2, b3_2,
                                    llb + ST_G256 * 512, out);
}

// round 15
// speedup vs baseline: 1.0665x; 1.0381x over previous
#include <cuda_runtime.h>
#include <cstdint>
#include <cstdio>

// ---------------------------------------------------------------------------
// LiBNet forward, batch 512.  Round 15 = R12 (405.8us, conv1 reverted to its
// best-measured spilled/high-occ form) + bn2_2 pool-select+sign fused into
// the stage-3 grouped conv's tile loader (float math from finalized
// g_mean/g_scale; removes 1 launch + a3 round trip). 10 launches.
// ---------------------------------------------------------------------------

#define BATCH 512

// Scratch (device globals)
__device__ float   g_y1mx[512u*256u*64u];  // conv1 window max [b,16,16,64]
__device__ float   g_y1mn[512u*256u*64u];  // conv1 window min
__device__ int8_t  g_a1[512u*256u*64u];    // sign(pool(bn1)) [b,16,16,64]
__device__ int8_t  g_y2b[512u*256u*64u];   // conv2_1 out int8
__device__ int8_t  g_y3mx[512u*64u*256u];  // gemm64 window max [b,8,8,256]
__device__ int8_t  g_y3mn[512u*64u*256u];  // gemm64 window min
__device__ int8_t  g_y4b[512u*64u*256u];   // conv3_1 out int8
__device__ int16_t g_y5s[512u*64u*256u];   // conv3_2 out int16
__device__ float   g_w1s[48*64];           // sign(w1) transposed [k][c]
__device__ int8_t  g_wg2[32*64];           // sign(w2_1) transposed [k][c]
__device__ int8_t  g_wg3[32*256];          // sign(w3_1) transposed [k][c]
__device__ int8_t  g_wp2[256*64];          // sign(w2_2)
__device__ int8_t  g_wp3[256*256];         // sign(w3_2)
__device__ float   g_part[2097152];        // float stats partials (conv1 only)
__device__ long long g_ll[4*512];          // int stats [stage][{sum,sq}][256]
__device__ float   g_mean[256];
__device__ float   g_scale[256];
__device__ float   g_fcwr[16384*10];       // fc_w n-major over NHWC-flatten

#define ST_GRP2   0
#define ST_GEMM64 1
#define ST_GRP3   2
#define ST_G256   3

__device__ __forceinline__ void atomAddLL(long long* p, long long v) {
    atomicAdd((unsigned long long*)p, (unsigned long long)v);
}

__device__ __forceinline__ void finalize_channel(const long long* sbuf,
                                                 const float* gamma, int c,
                                                 double Pd, float* pm_out,
                                                 float* ps_out) {
    double mean = (double)sbuf[c] / Pd;
    double var  = (double)sbuf[256 + c] / Pd - mean * mean;
    double inv  = (double)gamma[c] / sqrt(var + 1e-5);
    double sh   = rint(log2(fabs(inv) + 1e-12));
    if (sh > 4.0) sh = 4.0;
    if (sh < -4.0) sh = -4.0;
    double sgn = (inv > 0.0) ? 1.0 : ((inv < 0.0) ? -1.0 : 0.0);
    *pm_out = (float)mean;
    *ps_out = (float)(sgn * exp2(sh));
}

// ---------------------------------------------------------------------------
// prep: all weight packing + zero the integer stat buffers (single kernel).
// ---------------------------------------------------------------------------
__global__ void prep_kernel(const float* __restrict__ w1,
                            const float* __restrict__ w2_1,
                            const float* __restrict__ w3_1,
                            const float* __restrict__ w2_2,
                            const float* __restrict__ w3_2,
                            const float* __restrict__ fcw,
                            float* __restrict__ w1s,
                            int8_t* __restrict__ wg2,
                            int8_t* __restrict__ wg3,
                            int8_t* __restrict__ wp2,
                            int8_t* __restrict__ wp3,
                            float* __restrict__ fcwr,
                            long long* __restrict__ llbuf) {
    int bid = blockIdx.x, tid = threadIdx.x;
    if (bid < 640) {
        int i = bid * 256 + tid;  // fcwr: i = n*16384 + e, e = hw*256 + c
        int n = i / 16384;
        int e = i % 16384;
        int c = e & 255, hw = e >> 8;
        fcwr[i] = fcw[n * 16384 + c * 64 + hw];
    } else if (bid < 896) {
        int i = (bid - 640) * 256 + tid;
        float v = w3_2[i];
        wp3[i] = (int8_t)((v > 0.f) ? 1 : ((v < 0.f) ? -1 : 0));
    } else if (bid < 960) {
        int i = (bid - 896) * 256 + tid;
        float v = w2_2[i];
        wp2[i] = (int8_t)((v > 0.f) ? 1 : ((v < 0.f) ? -1 : 0));
    } else if (bid < 992) {
        int i = (bid - 960) * 256 + tid;  // i = k*256 + c
        int c = i & 255, k = i >> 8;
        float v = w3_1[c * 32 + k];
        wg3[i] = (int8_t)((v > 0.f) ? 1 : ((v < 0.f) ? -1 : 0));
    } else if (bid < 1000) {
        int i = (bid - 992) * 256 + tid;  // i = k*64 + c
        int c = i & 63, k = i >> 6;
        float v = w2_1[c * 32 + k];
        wg2[i] = (int8_t)((v > 0.f) ? 1 : ((v < 0.f) ? -1 : 0));
    } else if (bid < 1012) {
        int i = (bid - 1000) * 256 + tid;  // i = k*64 + c
        int c = i & 63, k = i >> 6;
        float v = w1[c * 48 + k];
        w1s[i] = (v > 0.f) ? 1.f : ((v < 0.f) ? -1.f : 0.f);
    } else {
#pragma unroll
        for (int q = 0; q < 8; q++) llbuf[q * 256 + tid] = 0;
    }
}

// ---------------------------------------------------------------------------
// conv1: verbatim R12 (best measured: ptxas default regs, high occupancy).
// ---------------------------------------------------------------------------
__global__ void conv1_kernel(const float* __restrict__ x,
                             const float* __restrict__ w1s,
                             float* __restrict__ ymx,
                             float* __restrict__ ymn) {
    const int NS = 4096;
    int b = blockIdx.y, oy0 = blockIdx.x * 4;
    int tid = threadIdx.x;
    int c = tid & 63, xq = tid >> 6;

    __shared__ float xs[3][7][36];
    __shared__ float2 sred[256];

    for (int i = tid; i < 3 * 7 * 36; i += 256) {
        int col = i % 36;
        int r   = (i / 36) % 7;
        int ci  = i / 252;
        int ix = col - 1, iy = oy0 - 1 + r;
        float v = 0.f;
        if (ix >= 0 && ix < 32 && iy >= 0 && iy < 32)
            v = x[(((size_t)b * 3 + ci) * 32 + iy) * 32 + ix];
        xs[ci][r][col] = v;
    }

    float wr[48];
#pragma unroll
    for (int k = 0; k < 48; k++) wr[k] = w1s[k * 64 + c];
    __syncthreads();

    float s1 = 0.f, s2 = 0.f;
    float pmx[4], pmn[4];
#pragma unroll
    for (int r = 0; r < 4; r++) {
        float acc[8];
#pragma unroll
        for (int j = 0; j < 8; j++) acc[j] = 0.f;
#pragma unroll
        for (int ci = 0; ci < 3; ci++) {
#pragma unroll
            for (int kh = 0; kh < 4; kh++) {
                float rx[11];
#pragma unroll
                for (int t = 0; t < 11; t++) rx[t] = xs[ci][r + kh][xq * 8 + t];
#pragma unroll
                for (int kw = 0; kw < 4; kw++) {
                    float wv = wr[ci * 16 + kh * 4 + kw];
#pragma unroll
                    for (int j = 0; j < 8; j++) acc[j] += wv * rx[j + kw];
                }
            }
        }
#pragma unroll
        for (int j = 0; j < 8; j++) {
            s1 += acc[j];
            s2 += acc[j] * acc[j];
        }
        if ((r & 1) == 0) {
#pragma unroll
            for (int p = 0; p < 4; p++) {
                pmx[p] = fmaxf(acc[2 * p], acc[2 * p + 1]);
                pmn[p] = fminf(acc[2 * p], acc[2 * p + 1]);
            }
        } else {
            int poy = (oy0 >> 1) + (r >> 1);
#pragma unroll
            for (int p = 0; p < 4; p++) {
                float wmx = fmaxf(pmx[p], fmaxf(acc[2 * p], acc[2 * p + 1]));
                float wmn = fminf(pmn[p], fminf(acc[2 * p], acc[2 * p + 1]));
                size_t oi = (((size_t)b * 16 + poy) * 16 + xq * 4 + p) * 64 + c;
                ymx[oi] = wmx;
                ymn[oi] = wmn;
            }
        }
    }

    sred[tid] = make_float2(s1, s2);
    __syncthreads();
    if (tid < 64) {
        float2 a = sred[tid], b1 = sred[tid + 64], c1 = sred[tid + 128],
               d1 = sred[tid + 192];
        int slice = b * 8 + blockIdx.x;
        g_part[tid * NS + slice]        = a.x + b1.x + c1.x + d1.x;
        g_part[(64 + tid) * NS + slice] = a.y + b1.y + c1.y + d1.y;
    }
}

// rf for conv1 (float partials), writes g_mean/g_scale
template <int C>
__global__ void reduce_finalize_kernel(const float* __restrict__ gamma,
                                       int nslices, int P) {
    int c = blockIdx.x;
    int tid = threadIdx.x;
    float s1 = 0.f, s2 = 0.f;
    const float* p1 = g_part + (size_t)c * nslices;
    const float* p2 = g_part + (size_t)(C + c) * nslices;
#pragma unroll 4
    for (int s = tid; s < nslices; s += 256) {
        s1 += p1[s];
        s2 += p2[s];
    }
    __shared__ double sd1[256], sd2[256];
    sd1[tid] = (double)s1;
    sd2[tid] = (double)s2;
    __syncthreads();
    for (int s = 128; s > 0; s >>= 1) {
        if (tid < s) {
            sd1[tid] += sd1[tid + s];
            sd2[tid] += sd2[tid + s];
        }
        __syncthreads();
    }
    if (tid == 0) {
        double mean = sd1[0] / (double)P;
        double var  = sd2[0] / (double)P - mean * mean;
        double inv  = (double)gamma[c] / sqrt(var + 1e-5);
        double sh   = rint(log2(fabs(inv) + 1e-12));
        if (sh > 4.0) sh = 4.0;
        if (sh < -4.0) sh = -4.0;
        double sgn = (inv > 0.0) ? 1.0 : ((inv < 0.0) ? -1.0 : 0.0);
        g_mean[c]  = (float)mean;
        g_scale[c] = (float)(sgn * exp2(sh));
    }
}

// tiny finalize from integer sums -> g_mean/g_scale (for bn2_2 consumer)
__global__ void finalize_ll_kernel(const long long* __restrict__ sbuf,
                                   const float* __restrict__ gamma, int P) {
    int c = threadIdx.x;
    finalize_channel(sbuf, gamma, c, (double)P, &g_mean[c], &g_scale[c]);
}

// ---------------------------------------------------------------------------
// BN + pool-select + sign, fp32 (stage 1). 4 ch/thread.
// ---------------------------------------------------------------------------
__global__ void bn_poolsel_sign4_f_kernel(const float* __restrict__ ymx,
                                          const float* __restrict__ ymn,
                                          int8_t* __restrict__ out,
                                          const float* __restrict__ beta,
                                          int total4) {
    int idx = blockIdx.x * 256 + threadIdx.x;
    if (idx >= total4) return;
    int c = (idx * 4) & 63;
    float4 m  = *(const float4*)(g_mean + c);
    float4 s  = *(const float4*)(g_scale + c);
    float4 bt = *(const float4*)(beta + c);
    float4 vx = ((const float4*)ymx)[idx];
    float4 vn = ((const float4*)ymn)[idx];
    float v0 = (s.x > 0.f) ? vx.x : vn.x;
    float v1 = (s.y > 0.f) ? vx.y : vn.y;
    float v2 = (s.z > 0.f) ? vx.z : vn.z;
    float v3 = (s.w > 0.f) ? vx.w : vn.w;
    float r0 = (v0 - m.x) * s.x + bt.x;
    float r1 = (v1 - m.y) * s.y + bt.y;
    float r2 = (v2 - m.z) * s.z + bt.z;
    float r3 = (v3 - m.w) * s.w + bt.w;
    char4 o;
    o.x = (char)((r0 > 0.f) ? 1 : ((r0 < 0.f) ? -1 : 0));
    o.y = (char)((r1 > 0.f) ? 1 : ((r1 < 0.f) ? -1 : 0));
    o.z = (char)((r2 > 0.f) ? 1 : ((r2 < 0.f) ? -1 : 0));
    o.w = (char)((r3 > 0.f) ? 1 : ((r3 < 0.f) ? -1 : 0));
    ((char4*)out)[idx] = o;
}

// ---------------------------------------------------------------------------
// Grouped 4x4 binary conv (stage 2, reads a1): int16-pair LDS + dp4a.
// ---------------------------------------------------------------------------
template <int H, int C>
__global__ void conv_grp_kernel(const int8_t* __restrict__ a,
                                const int8_t* __restrict__ wg,
                                int8_t* __restrict__ out,
                                long long* __restrict__ sbuf) {
    int b = blockIdx.y, oy = blockIdx.x;
    int tid = threadIdx.x;
    constexpr int PW = H + 3;
    __shared__ __align__(16) int8_t as[4][PW][C];
    __shared__ int2 sred[256];

    const int8_t* abase = a + (size_t)b * H * H * C;
    int total4 = (4 * PW * C) / 4;
    for (int i = tid; i < total4; i += 256) {
        int e = i * 4;
        int cc = e % C;
        int col = (e / C) % PW;
        int r = e / (C * PW);
        int ix = col - 1, iy = oy - 1 + r;
        int v = 0;
        if (ix >= 0 && ix < H && iy >= 0 && iy < H)
            v = *(const int*)(abase + ((size_t)iy * H + ix) * C + cc);
        *(int*)(&as[r][col][cc]) = v;
    }

    int c = tid % C;
    int xq = tid / C;
    int g2 = c & ~1;
    int wpair[16];
#pragma unroll
    for (int k = 0; k < 16; k++) {
        int w0 = (int)wg[k * C + c];
        int w1 = (int)wg[(16 + k) * C + c];
        wpair[k] = (w0 & 0xff) | ((w1 & 0xff) << 8);
    }
    __syncthreads();

    int is1 = 0, is2 = 0;
    constexpr int SPAN = (H * C) / 256;
    for (int j = 0; j < SPAN; j++) {
        int ox = xq * SPAN + j;
        int acc = 0;
#pragma unroll
        for (int kh = 0; kh < 4; kh++) {
#pragma unroll
            for (int kw = 0; kw < 4; kw++) {
                int v = (int)*(const uint16_t*)&as[kh][ox + kw][g2];
                acc = __dp4a(v, wpair[kh * 4 + kw], acc);
            }
        }
        out[(((size_t)b * H + oy) * H + ox) * C + c] = (int8_t)acc;
        is1 += acc;
        is2 += acc * acc;
    }

    sred[tid] = make_int2(is1, is2);
    __syncthreads();
    if (tid < C) {
        int a1 = 0, a2 = 0;
#pragma unroll
        for (int q = 0; q < 256 / C; q++) {
            a1 += sred[q * C + tid].x;
            a2 += sred[q * C + tid].y;
        }
        atomAddLL(&sbuf[tid], (long long)a1);
        atomAddLL(&sbuf[256 + tid], (long long)a2);
    }
}

// ---------------------------------------------------------------------------
// Stage-3 grouped conv with bn2_2 pool-select+sign FUSED into the tile
// loader: reads y3mx/y3mn + g_mean/g_scale (finalized) + beta; H=8, C=256.
// ---------------------------------------------------------------------------
__global__ void conv_grp_fused_kernel(const int8_t* __restrict__ ymx,
                                      const int8_t* __restrict__ ymn,
                                      const float* __restrict__ beta,
                                      const int8_t* __restrict__ wg,
                                      int8_t* __restrict__ out,
                                      long long* __restrict__ sbuf) {
    constexpr int H = 8, C = 256, PW = H + 3;
    int b = blockIdx.y, oy = blockIdx.x;
    int tid = threadIdx.x;
    __shared__ __align__(16) int8_t as[4][PW][C];

    const int8_t* xbase = ymx + (size_t)b * H * H * C;
    const int8_t* nbase = ymn + (size_t)b * H * H * C;
    int total4 = (4 * PW * C) / 4;
    for (int i = tid; i < total4; i += 256) {
        int e = i * 4;
        int cc = e % C;
        int col = (e / C) % PW;
        int r = e / (C * PW);
        int ix = col - 1, iy = oy - 1 + r;
        int pk = 0;
        if (ix >= 0 && ix < H && iy >= 0 && iy < H) {
            size_t off = ((size_t)iy * H + ix) * C + cc;
            char4 ux = *(const char4*)(xbase + off);
            char4 un = *(const char4*)(nbase + off);
            float4 m  = *(const float4*)(g_mean + cc);
            float4 s  = *(const float4*)(g_scale + cc);
            float4 bt = *(const float4*)(beta + cc);
            float v0 = (float)((s.x > 0.f) ? ux.x : un.x);
            float v1 = (float)((s.y > 0.f) ? ux.y : un.y);
            float v2 = (float)((s.z > 0.f) ? ux.z : un.z);
            float v3 = (float)((s.w > 0.f) ? ux.w : un.w);
            float r0 = (v0 - m.x) * s.x + bt.x;
            float r1 = (v1 - m.y) * s.y + bt.y;
            float r2 = (v2 - m.z) * s.z + bt.z;
            float r3 = (v3 - m.w) * s.w + bt.w;
            int u0 = (r0 > 0.f) ? 1 : ((r0 < 0.f) ? -1 : 0);
            int u1 = (r1 > 0.f) ? 1 : ((r1 < 0.f) ? -1 : 0);
            int u2 = (r2 > 0.f) ? 1 : ((r2 < 0.f) ? -1 : 0);
            int u3 = (r3 > 0.f) ? 1 : ((r3 < 0.f) ? -1 : 0);
            pk = (u0 & 0xff) | ((u1 & 0xff) << 8) | ((u2 & 0xff) << 16) |
                 (u3 << 24);
        }
        *(int*)(&as[r][col][cc]) = pk;
    }

    int c = tid;
    int wpair[16];
#pragma unroll
    for (int k = 0; k < 16; k++) {
        int w0 = (int)wg[k * C + c];
        int w1 = (int)wg[(16 + k) * C + c];
        wpair[k] = (w0 & 0xff) | ((w1 & 0xff) << 8);
    }
    int g2 = c & ~1;
    __syncthreads();

    int is1 = 0, is2 = 0;
    for (int j = 0; j < 8; j++) {
        int ox = j;
        int acc = 0;
#pragma unroll
        for (int kh = 0; kh < 4; kh++) {
#pragma unroll
            for (int kw = 0; kw < 4; kw++) {
                int v = (int)*(const uint16_t*)&as[kh][ox + kw][g2];
                acc = __dp4a(v, wpair[kh * 4 + kw], acc);
            }
        }
        out[(((size_t)b * H + oy) * H + ox) * C + c] = (int8_t)acc;
        is1 += acc;
        is2 += acc * acc;
    }

    atomAddLL(&sbuf[c], (long long)is1);
    atomAddLL(&sbuf[256 + c], (long long)is2);
}

// ---------------------------------------------------------------------------
// gemm64: inline bn2_1 finalize; pre-pool (max,min); stats via ll atomics.
// ---------------------------------------------------------------------------
__global__ void gemm64_kernel(const int8_t* __restrict__ yin,
                              const int8_t* __restrict__ wp,
                              const float* __restrict__ gamma,
                              const float* __restrict__ beta,
                              const long long* __restrict__ stat_in,
                              long long* __restrict__ stat_out,
                              int8_t* __restrict__ omx,
                              int8_t* __restrict__ omn) {
    __shared__ __align__(16) int as[128][16];
    __shared__ float pm[64], ps[64], pb[64];
    int tid = threadIdx.x;
    if (tid < 64) {
        finalize_channel(stat_in, gamma, tid, 131072.0, &pm[tid], &ps[tid]);
        pb[tid] = beta[tid];
    }
    int c = tid;
    int wr[16];
    const int* w4 = (const int*)wp + c * 16;
#pragma unroll
    for (int k = 0; k < 16; k++) wr[k] = w4[k];
    __syncthreads();

    size_t p0 = (size_t)blockIdx.x * 128;
    const int* y4 = (const int*)(yin + p0 * 64);
    for (int i = tid; i < 2048; i += 256) {
        int c0 = (i & 15) * 4;
        int v = y4[i];
        float r0 = ((float)(char)(v)       - pm[c0])     * ps[c0]     + pb[c0];
        float r1 = ((float)(char)(v >> 8)  - pm[c0 + 1]) * ps[c0 + 1] + pb[c0 + 1];
        float r2 = ((float)(char)(v >> 16) - pm[c0 + 2]) * ps[c0 + 2] + pb[c0 + 2];
        float r3 = ((float)(char)(v >> 24) - pm[c0 + 3]) * ps[c0 + 3] + pb[c0 + 3];
        int u0 = (r0 > 0.f) ? 1 : ((r0 < 0.f) ? -1 : 0);
        int u1 = (r1 > 0.f) ? 1 : ((r1 < 0.f) ? -1 : 0);
        int u2 = (r2 > 0.f) ? 1 : ((r2 < 0.f) ? -1 : 0);
        int u3 = (r3 > 0.f) ? 1 : ((r3 < 0.f) ? -1 : 0);
        as[i >> 4][i & 15] =
            (u0 & 0xff) | ((u1 & 0xff) << 8) | ((u2 & 0xff) << 16) | (u3 << 24);
    }
    __syncthreads();

    int bimg = blockIdx.x >> 1;
    int prow0 = (blockIdx.x & 1) * 4;
    int is1 = 0, is2 = 0;
    int rpx[8], rpn[8];
    for (int lr = 0; lr < 8; lr++) {
#pragma unroll
        for (int cp = 0; cp < 8; cp++) {
            int a0, a1;
#pragma unroll
            for (int h = 0; h < 2; h++) {
                int p = lr * 16 + cp * 2 + h;
                int acc = 0;
                const int4* av = (const int4*)as[p];
#pragma unroll
                for (int k4 = 0; k4 < 4; k4++) {
                    int4 v = av[k4];
                    acc = __dp4a(v.x, wr[k4 * 4 + 0], acc);
                    acc = __dp4a(v.y, wr[k4 * 4 + 1], acc);
                    acc = __dp4a(v.z, wr[k4 * 4 + 2], acc);
                    acc = __dp4a(v.w, wr[k4 * 4 + 3], acc);
                }
                is1 += acc;
                is2 += acc * acc;
                if (h == 0) a0 = acc; else a1 = acc;
            }
            int hx = max(a0, a1), hn = min(a0, a1);
            if ((lr & 1) == 0) {
                rpx[cp] = hx;
                rpn[cp] = hn;
            } else {
                int wmx = max(rpx[cp], hx);
                int wmn = min(rpn[cp], hn);
                size_t oi = (((size_t)bimg * 8 + prow0 + (lr >> 1)) * 8 + cp) * 256 + c;
                omx[oi] = (int8_t)wmx;
                omn[oi] = (int8_t)wmn;
            }
        }
    }
    atomAddLL(&stat_out[c], (long long)is1);
    atomAddLL(&stat_out[256 + c], (long long)is2);
}

// gemm256: inline bn3_1 finalize; stats via ll atomics.
__global__ void gemm256_kernel(const int8_t* __restrict__ yin,
                               const int8_t* __restrict__ wp,
                               const float* __restrict__ gamma,
                               const float* __restrict__ beta,
                               const long long* __restrict__ stat_in,
                               long long* __restrict__ stat_out,
                               int16_t* __restrict__ out) {
    __shared__ __align__(16) int as[64][64];
    __shared__ float pm[256], ps[256], pb[256];
    int tid = threadIdx.x;
    finalize_channel(stat_in, gamma, tid, 32768.0, &pm[tid], &ps[tid]);
    pb[tid] = beta[tid];
    int c = tid;
    int wr[64];
    const int* w4 = (const int*)wp + c * 64;
#pragma unroll
    for (int k = 0; k < 64; k++) wr[k] = w4[k];
    __syncthreads();

    size_t p0 = (size_t)blockIdx.x * 64;
    const int* y4 = (const int*)(yin + p0 * 256);
    for (int i = tid; i < 4096; i += 256) {
        int c0 = (i & 63) * 4;
        int v = y4[i];
        float r0 = ((float)(char)(v)       - pm[c0])     * ps[c0]     + pb[c0];
        float r1 = ((float)(char)(v >> 8)  - pm[c0 + 1]) * ps[c0 + 1] + pb[c0 + 1];
        float r2 = ((float)(char)(v >> 16) - pm[c0 + 2]) * ps[c0 + 2] + pb[c0 + 2];
        float r3 = ((float)(char)(v >> 24) - pm[c0 + 3]) * ps[c0 + 3] + pb[c0 + 3];
        int u0 = (r0 > 0.f) ? 1 : ((r0 < 0.f) ? -1 : 0);
        int u1 = (r1 > 0.f) ? 1 : ((r1 < 0.f) ? -1 : 0);
        int u2 = (r2 > 0.f) ? 1 : ((r2 < 0.f) ? -1 : 0);
        int u3 = (r3 > 0.f) ? 1 : ((r3 < 0.f) ? -1 : 0);
        as[i >> 6][i & 63] =
            (u0 & 0xff) | ((u1 & 0xff) << 8) | ((u2 & 0xff) << 16) | (u3 << 24);
    }
    __syncthreads();

    int is1 = 0, is2 = 0;
    for (int p = 0; p < 64; p++) {
        int acc = 0;
        const int4* av = (const int4*)as[p];
#pragma unroll
        for (int k4 = 0; k4 < 16; k4++) {
            int4 v = av[k4];
            acc = __dp4a(v.x, wr[k4 * 4 + 0], acc);
            acc = __dp4a(v.y, wr[k4 * 4 + 1], acc);
            acc = __dp4a(v.z, wr[k4 * 4 + 2], acc);
            acc = __dp4a(v.w, wr[k4 * 4 + 3], acc);
        }
        out[(p0 + p) * 256 + c] = (int16_t)acc;
        is1 += acc;
        is2 += acc * acc;
    }
    atomAddLL(&stat_out[c], (long long)is1);
    atomAddLL(&stat_out[256 + c], (long long)is2);
}

// ---------------------------------------------------------------------------
// FC with inline bn3_2 finalize; 4 batches per block; int16 input.
// ---------------------------------------------------------------------------
#define FCB 4
__global__ void fc_kernel(const int16_t* __restrict__ y5,
                          const float* __restrict__ fcwr,
                          const float* __restrict__ fc_b,
                          const float* __restrict__ gamma,
                          const float* __restrict__ beta,
                          const long long* __restrict__ stat_in,
                          float* __restrict__ out) {
    __shared__ float pm[256], ps[256], pb[256];
    int b0 = blockIdx.x * FCB;
    int tid = threadIdx.x;
    finalize_channel(stat_in, gamma, tid, 32768.0, &pm[tid], &ps[tid]);
    pb[tid] = beta[tid];
    __syncthreads();

    float acc[FCB][10];
#pragma unroll
    for (int bb = 0; bb < FCB; bb++)
#pragma unroll
        for (int n = 0; n < 10; n++) acc[bb][n] = 0.f;

    for (int i = tid; i < 16384; i += 256) {
        int c = i & 255;
        float m = pm[c], s = ps[c], bt = pb[c];
        float w[10];
#pragma unroll
        for (int n = 0; n < 10; n++) w[n] = fcwr[n * 16384 + i];
#pragma unroll
        for (int bb = 0; bb < FCB; bb++) {
            float v = ((float)y5[(size_t)(b0 + bb) * 16384 + i] - m) * s + bt;
#pragma unroll
            for (int n = 0; n < 10; n++) acc[bb][n] += v * w[n];
        }
    }

    __shared__ float sred[8][FCB * 10];
    int lane = tid & 31, wid = tid >> 5;
#pragma unroll
    for (int bb = 0; bb < FCB; bb++)
#pragma unroll
        for (int n = 0; n < 10; n++) {
            float v = acc[bb][n];
#pragma unroll
            for (int o = 16; o > 0; o >>= 1)
                v += __shfl_xor_sync(0xffffffffu, v, o);
            if (lane == 0) sred[wid][bb * 10 + n] = v;
        }
    __syncthreads();
    if (tid < FCB * 10) {
        float v = 0.f;
#pragma unroll
        for (int w8 = 0; w8 < 8; w8++) v += sred[w8][tid];
        int bb = tid / 10, n = tid % 10;
        out[(b0 + bb) * 10 + n] = v + fc_b[n];
    }
}

// ---------------------------------------------------------------------------
extern "C" void kernel_launch(void* const* d_in, const int* in_sizes, int n_in,
                              void* d_out, int out_size) {
    const float* x    = (const float*)d_in[0];
    const float* w1   = (const float*)d_in[1];
    const float* g1   = (const float*)d_in[2];
    const float* b1   = (const float*)d_in[3];
    const float* w2_1 = (const float*)d_in[4];
    const float* g2_1 = (const float*)d_in[5];
    const float* b2_1 = (const float*)d_in[6];
    const float* w2_2 = (const float*)d_in[7];
    const float* g2_2 = (const float*)d_in[8];
    const float* b2_2 = (const float*)d_in[9];
    const float* w3_1 = (const float*)d_in[10];
    const float* g3_1 = (const float*)d_in[11];
    const float* b3_1 = (const float*)d_in[12];
    const float* w3_2 = (const float*)d_in[13];
    const float* g3_2 = (const float*)d_in[14];
    const float* b3_2 = (const float*)d_in[15];
    const float* fcw  = (const float*)d_in[16];
    const float* fcb  = (const float*)d_in[17];
    float* out = (float*)d_out;

    float *y1mx, *y1mn, *fcwr, *w1s;
    int8_t *a1, *y2b, *y3mx, *y3mn, *y4b, *wp2, *wp3, *wg2, *wg3;
    int16_t *y5s;
    long long* llb;
    cudaGetSymbolAddress((void**)&y1mx, g_y1mx);
    cudaGetSymbolAddress((void**)&y1mn, g_y1mn);
    cudaGetSymbolAddress((void**)&y2b, g_y2b);
    cudaGetSymbolAddress((void**)&y3mx, g_y3mx);
    cudaGetSymbolAddress((void**)&y3mn, g_y3mn);
    cudaGetSymbolAddress((void**)&y4b, g_y4b);
    cudaGetSymbolAddress((void**)&y5s, g_y5s);
    cudaGetSymbolAddress((void**)&a1, g_a1);
    cudaGetSymbolAddress((void**)&wp2, g_wp2);
    cudaGetSymbolAddress((void**)&wp3, g_wp3);
    cudaGetSymbolAddress((void**)&wg2, g_wg2);
    cudaGetSymbolAddress((void**)&wg3, g_wg3);
    cudaGetSymbolAddress((void**)&fcwr, g_fcwr);
    cudaGetSymbolAddress((void**)&w1s, g_w1s);
    cudaGetSymbolAddress((void**)&llb, g_ll);

    // 1: weight prep + zero int stat buffers
    prep_kernel<<<1013, 256>>>(w1, w2_1, w3_1, w2_2, w3_2, fcw,
                               w1s, wg2, wg3, wp2, wp3, fcwr, llb);

    // 2-4: stage 1 (bn_poolsel_f in profiled slot 4 as control)
    conv1_kernel<<<dim3(8, BATCH), 256>>>(x, w1s, y1mx, y1mn);
    reduce_finalize_kernel<64><<<64, 256>>>(g1, 4096, 512 * 1024);
    bn_poolsel_sign4_f_kernel<<<(512 * 256 * 64 / 4 + 255) / 256, 256>>>(
        y1mx, y1mn, a1, b1, 512 * 256 * 64 / 4);

    // 5-7: stage 2
    conv_grp_kernel<16, 64><<<dim3(16, BATCH), 256>>>(a1, wg2, y2b,
                                                      llb + ST_GRP2 * 512);
    gemm64_kernel<<<(512 * 256) / 128, 256>>>(y2b, wp2, g2_1, b2_1,
                                              llb + ST_GRP2 * 512,
                                              llb + ST_GEMM64 * 512,
                                              y3mx, y3mn);
    finalize_ll_kernel<<<1, 256>>>(llb + ST_GEMM64 * 512, g2_2, 131072);

    // 8-9: stage 3 (bn2_2 pool-select+sign fused into grp3's loader)
    conv_grp_fused_kernel<<<dim3(8, BATCH), 256>>>(y3mx, y3mn, b2_2, wg3, y4b,
                                                   llb + ST_GRP3 * 512);
    gemm256_kernel<<<(512 * 64) / 64, 256>>>(y4b, wp3, g3_1, b3_1,
                                             llb + ST_GRP3 * 512,
                                             llb + ST_G256 * 512, y5s);

    // 10: FC (bn3_2 finalize inline)
    fc_kernel<<<BATCH / FCB, 256>>>(y5s, fcwr, fcb, g3_2, b3_2,
                                    llb + ST_G256 * 512, out);
}

// round 16
// speedup vs baseline: 1.0946x; 1.0263x over previous
#include <cuda_runtime.h>
#include <cstdint>
#include <cstdio>

// ---------------------------------------------------------------------------
// LiBNet forward, batch 512.  Round 16 = R15 (401.4us) + three amortizations:
//   (1) finalize_ll folded into conv_grp_fused prologue (9 launches)
//   (2) gemm64 tile 256 positions/block (512 blocks)
//   (3) gemm256 tile 128 positions/block (256 blocks)
// ---------------------------------------------------------------------------

#define BATCH 512

// Scratch (device globals)
__device__ float   g_y1mx[512u*256u*64u];  // conv1 window max [b,16,16,64]
__device__ float   g_y1mn[512u*256u*64u];  // conv1 window min
__device__ int8_t  g_a1[512u*256u*64u];    // sign(pool(bn1)) [b,16,16,64]
__device__ int8_t  g_y2b[512u*256u*64u];   // conv2_1 out int8
__device__ int8_t  g_y3mx[512u*64u*256u];  // gemm64 window max [b,8,8,256]
__device__ int8_t  g_y3mn[512u*64u*256u];  // gemm64 window min
__device__ int8_t  g_y4b[512u*64u*256u];   // conv3_1 out int8
__device__ int16_t g_y5s[512u*64u*256u];   // conv3_2 out int16
__device__ float   g_w1s[48*64];           // sign(w1) transposed [k][c]
__device__ int8_t  g_wg2[32*64];           // sign(w2_1) transposed [k][c]
__device__ int8_t  g_wg3[32*256];          // sign(w3_1) transposed [k][c]
__device__ int8_t  g_wp2[256*64];          // sign(w2_2)
__device__ int8_t  g_wp3[256*256];         // sign(w3_2)
__device__ float   g_part[2097152];        // float stats partials (conv1 only)
__device__ long long g_ll[4*512];          // int stats [stage][{sum,sq}][256]
__device__ float   g_mean[256];
__device__ float   g_scale[256];
__device__ float   g_fcwr[16384*10];       // fc_w n-major over NHWC-flatten

#define ST_GRP2   0
#define ST_GEMM64 1
#define ST_GRP3   2
#define ST_G256   3

__device__ __forceinline__ void atomAddLL(long long* p, long long v) {
    atomicAdd((unsigned long long*)p, (unsigned long long)v);
}

__device__ __forceinline__ void finalize_channel(const long long* sbuf,
                                                 const float* gamma, int c,
                                                 double Pd, float* pm_out,
                                                 float* ps_out) {
    double mean = (double)sbuf[c] / Pd;
    double var  = (double)sbuf[256 + c] / Pd - mean * mean;
    double inv  = (double)gamma[c] / sqrt(var + 1e-5);
    double sh   = rint(log2(fabs(inv) + 1e-12));
    if (sh > 4.0) sh = 4.0;
    if (sh < -4.0) sh = -4.0;
    double sgn = (inv > 0.0) ? 1.0 : ((inv < 0.0) ? -1.0 : 0.0);
    *pm_out = (float)mean;
    *ps_out = (float)(sgn * exp2(sh));
}

// ---------------------------------------------------------------------------
// prep: all weight packing + zero the integer stat buffers (single kernel).
// ---------------------------------------------------------------------------
__global__ void prep_kernel(const float* __restrict__ w1,
                            const float* __restrict__ w2_1,
                            const float* __restrict__ w3_1,
                            const float* __restrict__ w2_2,
                            const float* __restrict__ w3_2,
                            const float* __restrict__ fcw,
                            float* __restrict__ w1s,
                            int8_t* __restrict__ wg2,
                            int8_t* __restrict__ wg3,
                            int8_t* __restrict__ wp2,
                            int8_t* __restrict__ wp3,
                            float* __restrict__ fcwr,
                            long long* __restrict__ llbuf) {
    int bid = blockIdx.x, tid = threadIdx.x;
    if (bid < 640) {
        int i = bid * 256 + tid;  // fcwr: i = n*16384 + e, e = hw*256 + c
        int n = i / 16384;
        int e = i % 16384;
        int c = e & 255, hw = e >> 8;
        fcwr[i] = fcw[n * 16384 + c * 64 + hw];
    } else if (bid < 896) {
        int i = (bid - 640) * 256 + tid;
        float v = w3_2[i];
        wp3[i] = (int8_t)((v > 0.f) ? 1 : ((v < 0.f) ? -1 : 0));
    } else if (bid < 960) {
        int i = (bid - 896) * 256 + tid;
        float v = w2_2[i];
        wp2[i] = (int8_t)((v > 0.f) ? 1 : ((v < 0.f) ? -1 : 0));
    } else if (bid < 992) {
        int i = (bid - 960) * 256 + tid;  // i = k*256 + c
        int c = i & 255, k = i >> 8;
        float v = w3_1[c * 32 + k];
        wg3[i] = (int8_t)((v > 0.f) ? 1 : ((v < 0.f) ? -1 : 0));
    } else if (bid < 1000) {
        int i = (bid - 992) * 256 + tid;  // i = k*64 + c
        int c = i & 63, k = i >> 6;
        float v = w2_1[c * 32 + k];
        wg2[i] = (int8_t)((v > 0.f) ? 1 : ((v < 0.f) ? -1 : 0));
    } else if (bid < 1012) {
        int i = (bid - 1000) * 256 + tid;  // i = k*64 + c
        int c = i & 63, k = i >> 6;
        float v = w1[c * 48 + k];
        w1s[i] = (v > 0.f) ? 1.f : ((v < 0.f) ? -1.f : 0.f);
    } else {
#pragma unroll
        for (int q = 0; q < 8; q++) llbuf[q * 256 + tid] = 0;
    }
}

// ---------------------------------------------------------------------------
// conv1: verbatim R12 (best measured variant).
// ---------------------------------------------------------------------------
__global__ void conv1_kernel(const float* __restrict__ x,
                             const float* __restrict__ w1s,
                             float* __restrict__ ymx,
                             float* __restrict__ ymn) {
    const int NS = 4096;
    int b = blockIdx.y, oy0 = blockIdx.x * 4;
    int tid = threadIdx.x;
    int c = tid & 63, xq = tid >> 6;

    __shared__ float xs[3][7][36];
    __shared__ float2 sred[256];

    for (int i = tid; i < 3 * 7 * 36; i += 256) {
        int col = i % 36;
        int r   = (i / 36) % 7;
        int ci  = i / 252;
        int ix = col - 1, iy = oy0 - 1 + r;
        float v = 0.f;
        if (ix >= 0 && ix < 32 && iy >= 0 && iy < 32)
            v = x[(((size_t)b * 3 + ci) * 32 + iy) * 32 + ix];
        xs[ci][r][col] = v;
    }

    float wr[48];
#pragma unroll
    for (int k = 0; k < 48; k++) wr[k] = w1s[k * 64 + c];
    __syncthreads();

    float s1 = 0.f, s2 = 0.f;
    float pmx[4], pmn[4];
#pragma unroll
    for (int r = 0; r < 4; r++) {
        float acc[8];
#pragma unroll
        for (int j = 0; j < 8; j++) acc[j] = 0.f;
#pragma unroll
        for (int ci = 0; ci < 3; ci++) {
#pragma unroll
            for (int kh = 0; kh < 4; kh++) {
                float rx[11];
#pragma unroll
                for (int t = 0; t < 11; t++) rx[t] = xs[ci][r + kh][xq * 8 + t];
#pragma unroll
                for (int kw = 0; kw < 4; kw++) {
                    float wv = wr[ci * 16 + kh * 4 + kw];
#pragma unroll
                    for (int j = 0; j < 8; j++) acc[j] += wv * rx[j + kw];
                }
            }
        }
#pragma unroll
        for (int j = 0; j < 8; j++) {
            s1 += acc[j];
            s2 += acc[j] * acc[j];
        }
        if ((r & 1) == 0) {
#pragma unroll
            for (int p = 0; p < 4; p++) {
                pmx[p] = fmaxf(acc[2 * p], acc[2 * p + 1]);
                pmn[p] = fminf(acc[2 * p], acc[2 * p + 1]);
            }
        } else {
            int poy = (oy0 >> 1) + (r >> 1);
#pragma unroll
            for (int p = 0; p < 4; p++) {
                float wmx = fmaxf(pmx[p], fmaxf(acc[2 * p], acc[2 * p + 1]));
                float wmn = fminf(pmn[p], fminf(acc[2 * p], acc[2 * p + 1]));
                size_t oi = (((size_t)b * 16 + poy) * 16 + xq * 4 + p) * 64 + c;
                ymx[oi] = wmx;
                ymn[oi] = wmn;
            }
        }
    }

    sred[tid] = make_float2(s1, s2);
    __syncthreads();
    if (tid < 64) {
        float2 a = sred[tid], b1 = sred[tid + 64], c1 = sred[tid + 128],
               d1 = sred[tid + 192];
        int slice = b * 8 + blockIdx.x;
        g_part[tid * NS + slice]        = a.x + b1.x + c1.x + d1.x;
        g_part[(64 + tid) * NS + slice] = a.y + b1.y + c1.y + d1.y;
    }
}

// rf for conv1 (float partials), writes g_mean/g_scale
template <int C>
__global__ void reduce_finalize_kernel(const float* __restrict__ gamma,
                                       int nslices, int P) {
    int c = blockIdx.x;
    int tid = threadIdx.x;
    float s1 = 0.f, s2 = 0.f;
    const float* p1 = g_part + (size_t)c * nslices;
    const float* p2 = g_part + (size_t)(C + c) * nslices;
#pragma unroll 4
    for (int s = tid; s < nslices; s += 256) {
        s1 += p1[s];
        s2 += p2[s];
    }
    __shared__ double sd1[256], sd2[256];
    sd1[tid] = (double)s1;
    sd2[tid] = (double)s2;
    __syncthreads();
    for (int s = 128; s > 0; s >>= 1) {
        if (tid < s) {
            sd1[tid] += sd1[tid + s];
            sd2[tid] += sd2[tid + s];
        }
        __syncthreads();
    }
    if (tid == 0) {
        double mean = sd1[0] / (double)P;
        double var  = sd2[0] / (double)P - mean * mean;
        double inv  = (double)gamma[c] / sqrt(var + 1e-5);
        double sh   = rint(log2(fabs(inv) + 1e-12));
        if (sh > 4.0) sh = 4.0;
        if (sh < -4.0) sh = -4.0;
        double sgn = (inv > 0.0) ? 1.0 : ((inv < 0.0) ? -1.0 : 0.0);
        g_mean[c]  = (float)mean;
        g_scale[c] = (float)(sgn * exp2(sh));
    }
}

// ---------------------------------------------------------------------------
// BN + pool-select + sign, fp32 (stage 1). 4 ch/thread.
// ---------------------------------------------------------------------------
__global__ void bn_poolsel_sign4_f_kernel(const float* __restrict__ ymx,
                                          const float* __restrict__ ymn,
                                          int8_t* __restrict__ out,
                                          const float* __restrict__ beta,
                                          int total4) {
    int idx = blockIdx.x * 256 + threadIdx.x;
    if (idx >= total4) return;
    int c = (idx * 4) & 63;
    float4 m  = *(const float4*)(g_mean + c);
    float4 s  = *(const float4*)(g_scale + c);
    float4 bt = *(const float4*)(beta + c);
    float4 vx = ((const float4*)ymx)[idx];
    float4 vn = ((const float4*)ymn)[idx];
    float v0 = (s.x > 0.f) ? vx.x : vn.x;
    float v1 = (s.y > 0.f) ? vx.y : vn.y;
    float v2 = (s.z > 0.f) ? vx.z : vn.z;
    float v3 = (s.w > 0.f) ? vx.w : vn.w;
    float r0 = (v0 - m.x) * s.x + bt.x;
    float r1 = (v1 - m.y) * s.y + bt.y;
    float r2 = (v2 - m.z) * s.z + bt.z;
    float r3 = (v3 - m.w) * s.w + bt.w;
    char4 o;
    o.x = (char)((r0 > 0.f) ? 1 : ((r0 < 0.f) ? -1 : 0));
    o.y = (char)((r1 > 0.f) ? 1 : ((r1 < 0.f) ? -1 : 0));
    o.z = (char)((r2 > 0.f) ? 1 : ((r2 < 0.f) ? -1 : 0));
    o.w = (char)((r3 > 0.f) ? 1 : ((r3 < 0.f) ? -1 : 0));
    ((char4*)out)[idx] = o;
}

// ---------------------------------------------------------------------------
// Grouped 4x4 binary conv (stage 2, reads a1): int16-pair LDS + dp4a.
// ---------------------------------------------------------------------------
template <int H, int C>
__global__ void conv_grp_kernel(const int8_t* __restrict__ a,
                                const int8_t* __restrict__ wg,
                                int8_t* __restrict__ out,
                                long long* __restrict__ sbuf) {
    int b = blockIdx.y, oy = blockIdx.x;
    int tid = threadIdx.x;
    constexpr int PW = H + 3;
    __shared__ __align__(16) int8_t as[4][PW][C];
    __shared__ int2 sred[256];

    const int8_t* abase = a + (size_t)b * H * H * C;
    int total4 = (4 * PW * C) / 4;
    for (int i = tid; i < total4; i += 256) {
        int e = i * 4;
        int cc = e % C;
        int col = (e / C) % PW;
        int r = e / (C * PW);
        int ix = col - 1, iy = oy - 1 + r;
        int v = 0;
        if (ix >= 0 && ix < H && iy >= 0 && iy < H)
            v = *(const int*)(abase + ((size_t)iy * H + ix) * C + cc);
        *(int*)(&as[r][col][cc]) = v;
    }

    int c = tid % C;
    int xq = tid / C;
    int g2 = c & ~1;
    int wpair[16];
#pragma unroll
    for (int k = 0; k < 16; k++) {
        int w0 = (int)wg[k * C + c];
        int w1 = (int)wg[(16 + k) * C + c];
        wpair[k] = (w0 & 0xff) | ((w1 & 0xff) << 8);
    }
    __syncthreads();

    int is1 = 0, is2 = 0;
    constexpr int SPAN = (H * C) / 256;
    for (int j = 0; j < SPAN; j++) {
        int ox = xq * SPAN + j;
        int acc = 0;
#pragma unroll
        for (int kh = 0; kh < 4; kh++) {
#pragma unroll
            for (int kw = 0; kw < 4; kw++) {
                int v = (int)*(const uint16_t*)&as[kh][ox + kw][g2];
                acc = __dp4a(v, wpair[kh * 4 + kw], acc);
            }
        }
        out[(((size_t)b * H + oy) * H + ox) * C + c] = (int8_t)acc;
        is1 += acc;
        is2 += acc * acc;
    }

    sred[tid] = make_int2(is1, is2);
    __syncthreads();
    if (tid < C) {
        int a1 = 0, a2 = 0;
#pragma unroll
        for (int q = 0; q < 256 / C; q++) {
            a1 += sred[q * C + tid].x;
            a2 += sred[q * C + tid].y;
        }
        atomAddLL(&sbuf[tid], (long long)a1);
        atomAddLL(&sbuf[256 + tid], (long long)a2);
    }
}

// ---------------------------------------------------------------------------
// Stage-3 grouped conv; bn2_2 pool-select+sign fused in loader AND bn2_2
// finalize inlined in prologue (removes finalize_ll launch). H=8, C=256.
// ---------------------------------------------------------------------------
__global__ void conv_grp_fused_kernel(const int8_t* __restrict__ ymx,
                                      const int8_t* __restrict__ ymn,
                                      const float* __restrict__ gamma,
                                      const float* __restrict__ beta,
                                      const long long* __restrict__ stat_in,
                                      const int8_t* __restrict__ wg,
                                      int8_t* __restrict__ out,
                                      long long* __restrict__ sbuf) {
    constexpr int H = 8, C = 256, PW = H + 3;
    int b = blockIdx.y, oy = blockIdx.x;
    int tid = threadIdx.x;
    __shared__ __align__(16) int8_t as[4][PW][C];
    __shared__ __align__(16) float pm[256], ps[256], pb[256];

    finalize_channel(stat_in, gamma, tid, 131072.0, &pm[tid], &ps[tid]);
    pb[tid] = beta[tid];
    __syncthreads();

    const int8_t* xbase = ymx + (size_t)b * H * H * C;
    const int8_t* nbase = ymn + (size_t)b * H * H * C;
    int total4 = (4 * PW * C) / 4;
    for (int i = tid; i < total4; i += 256) {
        int e = i * 4;
        int cc = e % C;
        int col = (e / C) % PW;
        int r = e / (C * PW);
        int ix = col - 1, iy = oy - 1 + r;
        int pk = 0;
        if (ix >= 0 && ix < H && iy >= 0 && iy < H) {
            size_t off = ((size_t)iy * H + ix) * C + cc;
            char4 ux = *(const char4*)(xbase + off);
            char4 un = *(const char4*)(nbase + off);
            float4 m  = *(const float4*)(pm + cc);
            float4 s  = *(const float4*)(ps + cc);
            float4 bt = *(const float4*)(pb + cc);
            float v0 = (float)((s.x > 0.f) ? ux.x : un.x);
            float v1 = (float)((s.y > 0.f) ? ux.y : un.y);
            float v2 = (float)((s.z > 0.f) ? ux.z : un.z);
            float v3 = (float)((s.w > 0.f) ? ux.w : un.w);
            float r0 = (v0 - m.x) * s.x + bt.x;
            float r1 = (v1 - m.y) * s.y + bt.y;
            float r2 = (v2 - m.z) * s.z + bt.z;
            float r3 = (v3 - m.w) * s.w + bt.w;
            int u0 = (r0 > 0.f) ? 1 : ((r0 < 0.f) ? -1 : 0);
            int u1 = (r1 > 0.f) ? 1 : ((r1 < 0.f) ? -1 : 0);
            int u2 = (r2 > 0.f) ? 1 : ((r2 < 0.f) ? -1 : 0);
            int u3 = (r3 > 0.f) ? 1 : ((r3 < 0.f) ? -1 : 0);
            pk = (u0 & 0xff) | ((u1 & 0xff) << 8) | ((u2 & 0xff) << 16) |
                 (u3 << 24);
        }
        *(int*)(&as[r][col][cc]) = pk;
    }

    int c = tid;
    int wpair[16];
#pragma unroll
    for (int k = 0; k < 16; k++) {
        int w0 = (int)wg[k * C + c];
        int w1 = (int)wg[(16 + k) * C + c];
        wpair[k] = (w0 & 0xff) | ((w1 & 0xff) << 8);
    }
    int g2 = c & ~1;
    __syncthreads();

    int is1 = 0, is2 = 0;
    for (int j = 0; j < 8; j++) {
        int acc = 0;
#pragma unroll
        for (int kh = 0; kh < 4; kh++) {
#pragma unroll
            for (int kw = 0; kw < 4; kw++) {
                int v = (int)*(const uint16_t*)&as[kh][j + kw][g2];
                acc = __dp4a(v, wpair[kh * 4 + kw], acc);
            }
        }
        out[(((size_t)b * H + oy) * H + j) * C + c] = (int8_t)acc;
        is1 += acc;
        is2 += acc * acc;
    }

    atomAddLL(&sbuf[c], (long long)is1);
    atomAddLL(&sbuf[256 + c], (long long)is2);
}

// ---------------------------------------------------------------------------
// gemm64: 256 positions/block (512 blocks = one image per block). Inline
// bn2_1 finalize; pre-pool (max,min); stats via ll atomics.
// ---------------------------------------------------------------------------
__global__ void gemm64_kernel(const int8_t* __restrict__ yin,
                              const int8_t* __restrict__ wp,
                              const float* __restrict__ gamma,
                              const float* __restrict__ beta,
                              const long long* __restrict__ stat_in,
                              long long* __restrict__ stat_out,
                              int8_t* __restrict__ omx,
                              int8_t* __restrict__ omn) {
    __shared__ __align__(16) int as[256][16];
    __shared__ float pm[64], ps[64], pb[64];
    int tid = threadIdx.x;
    if (tid < 64) {
        finalize_channel(stat_in, gamma, tid, 131072.0, &pm[tid], &ps[tid]);
        pb[tid] = beta[tid];
    }
    int c = tid;
    int wr[16];
    const int* w4 = (const int*)wp + c * 16;
#pragma unroll
    for (int k = 0; k < 16; k++) wr[k] = w4[k];
    __syncthreads();

    size_t p0 = (size_t)blockIdx.x * 256;  // one 16x16 image
    const int* y4 = (const int*)(yin + p0 * 64);
    for (int i = tid; i < 4096; i += 256) {
        int c0 = (i & 15) * 4;
        int v = y4[i];
        float r0 = ((float)(char)(v)       - pm[c0])     * ps[c0]     + pb[c0];
        float r1 = ((float)(char)(v >> 8)  - pm[c0 + 1]) * ps[c0 + 1] + pb[c0 + 1];
        float r2 = ((float)(char)(v >> 16) - pm[c0 + 2]) * ps[c0 + 2] + pb[c0 + 2];
        float r3 = ((float)(char)(v >> 24) - pm[c0 + 3]) * ps[c0 + 3] + pb[c0 + 3];
        int u0 = (r0 > 0.f) ? 1 : ((r0 < 0.f) ? -1 : 0);
        int u1 = (r1 > 0.f) ? 1 : ((r1 < 0.f) ? -1 : 0);
        int u2 = (r2 > 0.f) ? 1 : ((r2 < 0.f) ? -1 : 0);
        int u3 = (r3 > 0.f) ? 1 : ((r3 < 0.f) ? -1 : 0);
        as[i >> 4][i & 15] =
            (u0 & 0xff) | ((u1 & 0xff) << 8) | ((u2 & 0xff) << 16) | (u3 << 24);
    }
    __syncthreads();

    int bimg = blockIdx.x;
    int is1 = 0, is2 = 0;
    int rpx[8], rpn[8];
    for (int lr = 0; lr < 16; lr++) {
#pragma unroll
        for (int cp = 0; cp < 8; cp++) {
            int a0, a1;
#pragma unroll
            for (int h = 0; h < 2; h++) {
                int p = lr * 16 + cp * 2 + h;
                int acc = 0;
                const int4* av = (const int4*)as[p];
#pragma unroll
                for (int k4 = 0; k4 < 4; k4++) {
                    int4 v = av[k4];
                    acc = __dp4a(v.x, wr[k4 * 4 + 0], acc);
                    acc = __dp4a(v.y, wr[k4 * 4 + 1], acc);
                    acc = __dp4a(v.z, wr[k4 * 4 + 2], acc);
                    acc = __dp4a(v.w, wr[k4 * 4 + 3], acc);
                }
                is1 += acc;
                is2 += acc * acc;
                if (h == 0) a0 = acc; else a1 = acc;
            }
            int hx = max(a0, a1), hn = min(a0, a1);
            if ((lr & 1) == 0) {
                rpx[cp] = hx;
                rpn[cp] = hn;
            } else {
                int wmx = max(rpx[cp], hx);
                int wmn = min(rpn[cp], hn);
                size_t oi = (((size_t)bimg * 8 + (lr >> 1)) * 8 + cp) * 256 + c;
                omx[oi] = (int8_t)wmx;
                omn[oi] = (int8_t)wmn;
            }
        }
    }
    atomAddLL(&stat_out[c], (long long)is1);
    atomAddLL(&stat_out[256 + c], (long long)is2);
}

// gemm256: 128 positions/block (256 blocks). Inline bn3_1 finalize.
__global__ void gemm256_kernel(const int8_t* __restrict__ yin,
                               const int8_t* __restrict__ wp,
                               const float* __restrict__ gamma,
                               const float* __restrict__ beta,
                               const long long* __restrict__ stat_in,
                               long long* __restrict__ stat_out,
                               int16_t* __restrict__ out) {
    __shared__ __align__(16) int as[128][64];
    __shared__ float pm[256], ps[256], pb[256];
    int tid = threadIdx.x;
    finalize_channel(stat_in, gamma, tid, 32768.0, &pm[tid], &ps[tid]);
    pb[tid] = beta[tid];
    int c = tid;
    int wr[64];
    const int* w4 = (const int*)wp + c * 64;
#pragma unroll
    for (int k = 0; k < 64; k++) wr[k] = w4[k];
    __syncthreads();

    size_t p0 = (size_t)blockIdx.x * 128;
    const int* y4 = (const int*)(yin + p0 * 256);
    for (int i = tid; i < 8192; i += 256) {
        int c0 = (i & 63) * 4;
        int v = y4[i];
        float r0 = ((float)(char)(v)       - pm[c0])     * ps[c0]     + pb[c0];
        float r1 = ((float)(char)(v >> 8)  - pm[c0 + 1]) * ps[c0 + 1] + pb[c0 + 1];
        float r2 = ((float)(char)(v >> 16) - pm[c0 + 2]) * ps[c0 + 2] + pb[c0 + 2];
        float r3 = ((float)(char)(v >> 24) - pm[c0 + 3]) * ps[c0 + 3] + pb[c0 + 3];
        int u0 = (r0 > 0.f) ? 1 : ((r0 < 0.f) ? -1 : 0);
        int u1 = (r1 > 0.f) ? 1 : ((r1 < 0.f) ? -1 : 0);
        int u2 = (r2 > 0.f) ? 1 : ((r2 < 0.f) ? -1 : 0);
        int u3 = (r3 > 0.f) ? 1 : ((r3 < 0.f) ? -1 : 0);
        as[i >> 6][i & 63] =
            (u0 & 0xff) | ((u1 & 0xff) << 8) | ((u2 & 0xff) << 16) | (u3 << 24);
    }
    __syncthreads();

    int is1 = 0, is2 = 0;
    for (int p = 0; p < 128; p++) {
        int acc = 0;
        const int4* av = (const int4*)as[p];
#pragma unroll
        for (int k4 = 0; k4 < 16; k4++) {
            int4 v = av[k4];
            acc = __dp4a(v.x, wr[k4 * 4 + 0], acc);
            acc = __dp4a(v.y, wr[k4 * 4 + 1], acc);
            acc = __dp4a(v.z, wr[k4 * 4 + 2], acc);
            acc = __dp4a(v.w, wr[k4 * 4 + 3], acc);
        }
        out[(p0 + p) * 256 + c] = (int16_t)acc;
        is1 += acc;
        is2 += acc * acc;
    }
    atomAddLL(&stat_out[c], (long long)is1);
    atomAddLL(&stat_out[256 + c], (long long)is2);
}

// ---------------------------------------------------------------------------
// FC with inline bn3_2 finalize; 4 batches per block; int16 input.
// ---------------------------------------------------------------------------
#define FCB 4
__global__ void fc_kernel(const int16_t* __restrict__ y5,
                          const float* __restrict__ fcwr,
                          const float* __restrict__ fc_b,
                          const float* __restrict__ gamma,
                          const float* __restrict__ beta,
                          const long long* __restrict__ stat_in,
                          float* __restrict__ out) {
    __shared__ float pm[256], ps[256], pb[256];
    int b0 = blockIdx.x * FCB;
    int tid = threadIdx.x;
    finalize_channel(stat_in, gamma, tid, 32768.0, &pm[tid], &ps[tid]);
    pb[tid] = beta[tid];
    __syncthreads();

    float acc[FCB][10];
#pragma unroll
    for (int bb = 0; bb < FCB; bb++)
#pragma unroll
        for (int n = 0; n < 10; n++) acc[bb][n] = 0.f;

    for (int i = tid; i < 16384; i += 256) {
        int c = i & 255;
        float m = pm[c], s = ps[c], bt = pb[c];
        float w[10];
#pragma unroll
        for (int n = 0; n < 10; n++) w[n] = fcwr[n * 16384 + i];
#pragma unroll
        for (int bb = 0; bb < FCB; bb++) {
            float v = ((float)y5[(size_t)(b0 + bb) * 16384 + i] - m) * s + bt;
#pragma unroll
            for (int n = 0; n < 10; n++) acc[bb][n] += v * w[n];
        }
    }

    __shared__ float sred[8][FCB * 10];
    int lane = tid & 31, wid = tid >> 5;
#pragma unroll
    for (int bb = 0; bb < FCB; bb++)
#pragma unroll
        for (int n = 0; n < 10; n++) {
            float v = acc[bb][n];
#pragma unroll
            for (int o = 16; o > 0; o >>= 1)
                v += __shfl_xor_sync(0xffffffffu, v, o);
            if (lane == 0) sred[wid][bb * 10 + n] = v;
        }
    __syncthreads();
    if (tid < FCB * 10) {
        float v = 0.f;
#pragma unroll
        for (int w8 = 0; w8 < 8; w8++) v += sred[w8][tid];
        int bb = tid / 10, n = tid % 10;
        out[(b0 + bb) * 10 + n] = v + fc_b[n];
    }
}

// ---------------------------------------------------------------------------
extern "C" void kernel_launch(void* const* d_in, const int* in_sizes, int n_in,
                              void* d_out, int out_size) {
    const float* x    = (const float*)d_in[0];
    const float* w1   = (const float*)d_in[1];
    const float* g1   = (const float*)d_in[2];
    const float* b1   = (const float*)d_in[3];
    const float* w2_1 = (const float*)d_in[4];
    const float* g2_1 = (const float*)d_in[5];
    const float* b2_1 = (const float*)d_in[6];
    const float* w2_2 = (const float*)d_in[7];
    const float* g2_2 = (const float*)d_in[8];
    const float* b2_2 = (const float*)d_in[9];
    const float* w3_1 = (const float*)d_in[10];
    const float* g3_1 = (const float*)d_in[11];
    const float* b3_1 = (const float*)d_in[12];
    const float* w3_2 = (const float*)d_in[13];
    const float* g3_2 = (const float*)d_in[14];
    const float* b3_2 = (const float*)d_in[15];
    const float* fcw  = (const float*)d_in[16];
    const float* fcb  = (const float*)d_in[17];
    float* out = (float*)d_out;

    float *y1mx, *y1mn, *fcwr, *w1s;
    int8_t *a1, *y2b, *y3mx, *y3mn, *y4b, *wp2, *wp3, *wg2, *wg3;
    int16_t *y5s;
    long long* llb;
    cudaGetSymbolAddress((void**)&y1mx, g_y1mx);
    cudaGetSymbolAddress((void**)&y1mn, g_y1mn);
    cudaGetSymbolAddress((void**)&y2b, g_y2b);
    cudaGetSymbolAddress((void**)&y3mx, g_y3mx);
    cudaGetSymbolAddress((void**)&y3mn, g_y3mn);
    cudaGetSymbolAddress((void**)&y4b, g_y4b);
    cudaGetSymbolAddress((void**)&y5s, g_y5s);
    cudaGetSymbolAddress((void**)&a1, g_a1);
    cudaGetSymbolAddress((void**)&wp2, g_wp2);
    cudaGetSymbolAddress((void**)&wp3, g_wp3);
    cudaGetSymbolAddress((void**)&wg2, g_wg2);
    cudaGetSymbolAddress((void**)&wg3, g_wg3);
    cudaGetSymbolAddress((void**)&fcwr, g_fcwr);
    cudaGetSymbolAddress((void**)&w1s, g_w1s);
    cudaGetSymbolAddress((void**)&llb, g_ll);

    // 1: weight prep + zero int stat buffers
    prep_kernel<<<1013, 256>>>(w1, w2_1, w3_1, w2_2, w3_2, fcw,
                               w1s, wg2, wg3, wp2, wp3, fcwr, llb);

    // 2-4: stage 1 (bn_poolsel_f in profiled slot 4 as control)
    conv1_kernel<<<dim3(8, BATCH), 256>>>(x, w1s, y1mx, y1mn);
    reduce_finalize_kernel<64><<<64, 256>>>(g1, 4096, 512 * 1024);
    bn_poolsel_sign4_f_kernel<<<(512 * 256 * 64 / 4 + 255) / 256, 256>>>(
        y1mx, y1mn, a1, b1, 512 * 256 * 64 / 4);

    // 5-6: stage 2
    conv_grp_kernel<16, 64><<<dim3(16, BATCH), 256>>>(a1, wg2, y2b,
                                                      llb + ST_GRP2 * 512);
    gemm64_kernel<<<512, 256>>>(y2b, wp2, g2_1, b2_1,
                                llb + ST_GRP2 * 512,
                                llb + ST_GEMM64 * 512, y3mx, y3mn);

    // 7-8: stage 3 (bn2_2 finalize + pool-select+sign fused into grp3)
    conv_grp_fused_kernel<<<dim3(8, BATCH), 256>>>(
        y3mx, y3mn, g2_2, b2_2, llb + ST_GEMM64 * 512, wg3, y4b,
        llb + ST_GRP3 * 512);
    gemm256_kernel<<<256, 256>>>(y4b, wp3, g3_1, b3_1,
                                 llb + ST_GRP3 * 512,
                                 llb + ST_G256 * 512, y5s);

    // 9: FC (bn3_2 finalize inline)
    fc_kernel<<<BATCH / FCB, 256>>>(y5s, fcwr, fcb, g3_2, b3_2,
                                    llb + ST_G256 * 512, out);
}